// round 5
// baseline (speedup 1.0000x reference)
#include <cuda_runtime.h>
#include <math.h>

#define MD 1024
#define ND 4096
#define BD 16
#define KK 32
#define KK2 64
#define SMX 512
#define NITER 8
#define MSPLIT 8
#define TOLSQ (1e-6f * 1e-6f)
#define PAD 72

typedef unsigned long long u64_t;
__device__ __forceinline__ void fma2(u64_t &d, u64_t a, u64_t b) {
    asm("fma.rn.f32x2 %0, %1, %2, %0;" : "+l"(d) : "l"(a), "l"(b));
}
__device__ __forceinline__ float acc2sum(u64_t v) {
    float lo, hi; asm("mov.b64 {%0,%1}, %2;" : "=f"(lo), "=f"(hi) : "l"(v)); return lo + hi;
}

// ---------------- persistent device state ----------------
__device__ __align__(16) float g_AT[ND][MD];                 // A transposed
__device__ __align__(16) float g_rT[MD][BD];                 // residual transposed [m][b]
__device__ __align__(16) float g_partial[MSPLIT][BD][ND];    // proxy partial sums
__device__ unsigned char g_support[BD][ND];
__device__ int   g_suplist[BD][SMX];
__device__ int   g_scount[BD];
__device__ int   g_sold[BD];
__device__ int   g_done[BD];
__device__ __align__(16) float g_P[BD][SMX][MD];             // packed support columns
__device__ __align__(16) float g_G[BD][SMX][SMX];            // Gram (insertion order)
__device__ __align__(16) float g_H[BD][SMX][SMX];            // running inverse of G
__device__ float g_c[BD][SMX];                               // A_sub^T y
__device__ __align__(16) float g_T1[BD][SMX][KK2];           // H*G12 (pad cols zeroed)
__device__ float g_Sinv[BD][KK2][KK2];                       // padded-identity inverse
__device__ int   g_xcols[BD][KK];
__device__ float g_xvals[BD][KK];

// ---------------- one-time: transpose A ----------------
__global__ void k_transpose(const float* __restrict__ A) {
    __shared__ float tile[32][33];
    int nb = blockIdx.x * 32, mb = blockIdx.y * 32;
    int tx = threadIdx.x, ty = threadIdx.y;
    for (int i = ty; i < 32; i += 8)
        tile[i][tx] = A[(size_t)(mb + i) * ND + nb + tx];
    __syncthreads();
    for (int i = ty; i < 32; i += 8)
        g_AT[nb + i][mb + tx] = tile[tx][i];
}

// ---------------- init ----------------
__global__ void k_init(const float* __restrict__ meas) {
    int i = blockIdx.x * blockDim.x + threadIdx.x;
    int stride = gridDim.x * blockDim.x;
    for (int t = i; t < BD * ND; t += stride) g_support[t / ND][t % ND] = 0;
    if (i < BD * MD) { int b = i / MD, m = i % MD; g_rT[m][b] = meas[b * MD + m]; }
    if (i < BD) { g_scount[i] = 0; g_sold[i] = 0; g_done[i] = 0; }
}

// ---------------- proxy = A^T r, m-split partials ----------------
// grid (4, 4, MSPLIT), block 256
__global__ void k_proxy(const float* __restrict__ A) {
    int t  = threadIdx.x;
    int n0 = (blockIdx.x * 256 + t) * 4;
    int bg = blockIdx.y * 4;
    int mz = blockIdx.z;
    int m0 = mz * (MD / MSPLIT);
    float acc[4][4] = {};
    #pragma unroll 4
    for (int mm = 0; mm < MD / MSPLIT; mm++) {
        int m = m0 + mm;
        float4 a  = *(const float4*)(A + (size_t)m * ND + n0);
        float4 rv = *(const float4*)(&g_rT[m][bg]);
        acc[0][0] = fmaf(a.x, rv.x, acc[0][0]); acc[0][1] = fmaf(a.y, rv.x, acc[0][1]);
        acc[0][2] = fmaf(a.z, rv.x, acc[0][2]); acc[0][3] = fmaf(a.w, rv.x, acc[0][3]);
        acc[1][0] = fmaf(a.x, rv.y, acc[1][0]); acc[1][1] = fmaf(a.y, rv.y, acc[1][1]);
        acc[1][2] = fmaf(a.z, rv.y, acc[1][2]); acc[1][3] = fmaf(a.w, rv.y, acc[1][3]);
        acc[2][0] = fmaf(a.x, rv.z, acc[2][0]); acc[2][1] = fmaf(a.y, rv.z, acc[2][1]);
        acc[2][2] = fmaf(a.z, rv.z, acc[2][2]); acc[2][3] = fmaf(a.w, rv.z, acc[2][3]);
        acc[3][0] = fmaf(a.x, rv.w, acc[3][0]); acc[3][1] = fmaf(a.y, rv.w, acc[3][1]);
        acc[3][2] = fmaf(a.z, rv.w, acc[3][2]); acc[3][3] = fmaf(a.w, rv.w, acc[3][3]);
    }
    #pragma unroll
    for (int bb = 0; bb < 4; bb++) {
        float4 v = make_float4(acc[bb][0], acc[bb][1], acc[bb][2], acc[bb][3]);
        *(float4*)(&g_partial[mz][bg + bb][n0]) = v;
    }
}

// ---------------- radix-select top-64 (warp-parallel scan) + support update ----------------
// grid BD, block 512
__global__ void k_topk(void) {
    const int BT = 512;
    int b = blockIdx.x;
    if (g_done[b]) return;
    __shared__ unsigned keys[ND];
    __shared__ int hist[4][256];
    __shared__ unsigned sh_pref; __shared__ int sh_need;
    __shared__ int eqlist[128];
    __shared__ int sh_neq, sh_app, sh_sold;
    int t = threadIdx.x;
    for (int n = t; n < ND; n += BT) {
        float s = 0.f;
        #pragma unroll
        for (int ms = 0; ms < MSPLIT; ms++) s += g_partial[ms][b][n];
        keys[n] = __float_as_uint(fabsf(s));
    }
    if (t == 0) { sh_sold = g_scount[b]; sh_app = sh_sold; sh_neq = 0; }
    __syncthreads();
    unsigned pref = 0; int need = 2 * KK;
    for (int shift = 24; shift >= 0; shift -= 8) {
        unsigned mhi = (shift == 24) ? 0u : (0xFFFFFFFFu << (shift + 8));
        for (int i = t; i < 1024; i += BT) hist[i >> 8][i & 255] = 0;
        __syncthreads();
        int hs = (t >> 5) & 3;
        for (int n = t; n < ND; n += BT) {
            unsigned k = keys[n];
            if ((k & mhi) == pref) atomicAdd(&hist[hs][(k >> shift) & 255], 1);
        }
        __syncthreads();
        if (t < 256) hist[0][t] += hist[1][t] + hist[2][t] + hist[3][t];
        __syncthreads();
        if (t < 32) {
            int base = 255 - 8 * t;
            int cnt[8]; int ssum = 0;
            #pragma unroll
            for (int q = 0; q < 8; q++) { cnt[q] = hist[0][base - q]; ssum += cnt[q]; }
            int incl = ssum;
            #pragma unroll
            for (int off = 1; off < 32; off <<= 1) {
                int v = __shfl_up_sync(0xffffffffu, incl, off);
                if (t >= off) incl += v;
            }
            int excl = incl - ssum;
            if (excl < need && need <= incl) {
                int cum = excl;
                #pragma unroll
                for (int q = 0; q < 8; q++) {
                    cum += cnt[q];
                    if (cum >= need) {
                        sh_pref = pref | ((unsigned)(base - q) << shift);
                        sh_need = need - (cum - cnt[q]);
                        break;
                    }
                }
            }
        }
        __syncthreads();
        pref = sh_pref; need = sh_need;
        __syncthreads();
    }
    unsigned T = pref;
    // single unordered selection pass (append order is irrelevant; ties handled below)
    for (int n = t; n < ND; n += BT) {
        unsigned k = keys[n];
        if (k > T) {
            if (!g_support[b][n]) {
                g_support[b][n] = 1;
                int p = atomicAdd(&sh_app, 1);
                g_suplist[b][p] = n;
            }
        } else if (k == T) {
            int q = atomicAdd(&sh_neq, 1);
            if (q < 128) eqlist[q] = n;
        }
    }
    __syncthreads();
    if (t == 0) {
        int ne = sh_neq < 128 ? sh_neq : 128;
        for (int r = 0; r < need; r++) {           // jax ties: smallest index first
            int best = 0x7fffffff, bi = -1;
            for (int q = 0; q < ne; q++) {
                int n = eqlist[q];
                if (n >= 0 && n < best) { best = n; bi = q; }
            }
            if (bi < 0) break;
            eqlist[bi] = -1;
            if (!g_support[b][best]) {
                g_support[b][best] = 1;
                g_suplist[b][sh_app++] = best;
            }
        }
        g_sold[b] = sh_sold;
        g_scount[b] = sh_app;
    }
}

// ---------------- pack new columns (coalesced via AT) + c = P_new^T y ----------------
// grid (BD, KK2), block 128
__global__ void k_pack(const float* __restrict__ meas) {
    int b = blockIdx.x;
    if (g_done[b]) return;
    int so = g_sold[b], s = g_scount[b];
    int p = so + blockIdx.y;
    if (p >= s) return;
    int col = g_suplist[b][p];
    int t = threadIdx.x;
    const float4* Acol = (const float4*)g_AT[col];
    const float4* Y    = (const float4*)(meas + (size_t)b * MD);
    float4* Pd = (float4*)g_P[b][p];
    float acc = 0.f;
    #pragma unroll
    for (int i = 0; i < 2; i++) {
        int idx = t + i * 128;
        float4 v = Acol[idx]; float4 yv = Y[idx];
        Pd[idx] = v;
        acc = fmaf(v.x, yv.x, fmaf(v.y, yv.y, fmaf(v.z, yv.z, fmaf(v.w, yv.w, acc))));
    }
    __shared__ float red[4];
    #pragma unroll
    for (int off = 16; off; off >>= 1) acc += __shfl_down_sync(0xffffffffu, acc, off);
    if ((t & 31) == 0) red[t >> 5] = acc;
    __syncthreads();
    if (t == 0) g_c[b][p] = red[0] + red[1] + red[2] + red[3];
}

// ======== shared 64x64 microkernel body (f32x2 packed FMA) ========
#define MICROKERNEL(ASRC, BSRC)                                             \
    {                                                                       \
        _Pragma("unroll")                                                   \
        for (int k4 = 0; k4 < 16; k4++) {                                   \
            ulonglong2 rv[4], cv[4];                                        \
            _Pragma("unroll")                                               \
            for (int i = 0; i < 4; i++)                                     \
                rv[i] = *(const ulonglong2*)&ASRC[(ty * 4 + i) * PAD + k4 * 4]; \
            _Pragma("unroll")                                               \
            for (int j = 0; j < 4; j++)                                     \
                cv[j] = *(const ulonglong2*)&BSRC[(tx * 4 + j) * PAD + k4 * 4]; \
            _Pragma("unroll")                                               \
            for (int i = 0; i < 4; i++)                                     \
                _Pragma("unroll")                                           \
                for (int j = 0; j < 4; j++) {                               \
                    fma2(acc2[i][j], rv[i].x, cv[j].x);                     \
                    fma2(acc2[i][j], rv[i].y, cv[j].y);                     \
                }                                                           \
        }                                                                   \
    }

// ---------------- Gram new rows: G[so+r][c] = Pnew @ Pall^T ----------------
// grid (BD, 8), block 256
__global__ void k_gram(void) {
    int b = blockIdx.x;
    if (g_done[b]) return;
    int so = g_sold[b], s = g_scount[b], nn = s - so;
    if (nn == 0) return;
    int c0 = blockIdx.y * 64;
    if (c0 >= s) return;
    __shared__ float As[64 * PAD], Bs[64 * PAD];
    int t = threadIdx.x;
    int ty = t >> 4, tx = t & 15;
    u64_t acc2[4][4] = {};
    for (int k0 = 0; k0 < MD; k0 += 64) {
        for (int idx = t; idx < 64 * 64; idx += 256) {
            int rr = idx >> 6, kk = idx & 63;
            As[rr * PAD + kk] = (rr < nn) ? g_P[b][so + rr][k0 + kk] : 0.f;
            Bs[rr * PAD + kk] = (c0 + rr < s) ? g_P[b][c0 + rr][k0 + kk] : 0.f;
        }
        __syncthreads();
        MICROKERNEL(As, Bs)
        __syncthreads();
    }
    #pragma unroll
    for (int i = 0; i < 4; i++) {
        int r = ty * 4 + i; if (r >= nn) continue;
        #pragma unroll
        for (int j = 0; j < 4; j++) {
            int c = c0 + tx * 4 + j; if (c >= s) continue;
            float v = acc2sum(acc2[i][j]);
            g_G[b][so + r][c] = v;
            g_G[b][c][so + r] = v;
        }
    }
}

// ---------------- T1^T formulation: T1t[c][r] = sum_k G[so+c][k] * H[r][k] ----------------
// writes g_T1[r][c] (pad cols c>=nn zeroed).  grid (BD, 8), block 256
__global__ void k_T1(void) {
    int b = blockIdx.x;
    if (g_done[b]) return;
    int so = g_sold[b], s = g_scount[b], nn = s - so;
    if (nn == 0) return;
    int r0 = blockIdx.y * 64;
    if (r0 >= so) return;
    __shared__ float As[64 * PAD], Bs[64 * PAD];
    int t = threadIdx.x;
    int ty = t >> 4, tx = t & 15;
    u64_t acc2[4][4] = {};
    for (int k0 = 0; k0 < so; k0 += 64) {
        for (int idx = t; idx < 64 * 64; idx += 256) {
            int rr = idx >> 6, kk = idx & 63;
            As[rr * PAD + kk] = (rr < nn && k0 + kk < so) ? g_G[b][so + rr][k0 + kk] : 0.f;
            Bs[rr * PAD + kk] = (r0 + rr < so && k0 + kk < so) ? g_H[b][r0 + rr][k0 + kk] : 0.f;
        }
        __syncthreads();
        MICROKERNEL(As, Bs)
        __syncthreads();
    }
    #pragma unroll
    for (int i = 0; i < 4; i++) {
        int c = ty * 4 + i;
        #pragma unroll
        for (int j = 0; j < 4; j++) {
            int r = r0 + tx * 4 + j;
            if (r < so) g_T1[b][r][c] = acc2sum(acc2[i][j]);  // pad cols write 0
        }
    }
}

// ---------------- fused: S = G22 - G21 T1 (smem) -> GJ inverse -> Sinv, H22 ----------------
// grid BD, block 512
__global__ void k_SSinv(void) {
    int b = blockIdx.x;
    if (g_done[b]) return;
    int so = g_sold[b], s = g_scount[b], nn = s - so;
    if (nn == 0) return;
    __shared__ float Gs[64][65], Ts[64][65];
    __shared__ float pivrow[128], fcol[64], sh_piv;
    int t = threadIdx.x;
    int i = t >> 3, jg = t & 7;
    float accs[8] = {};
    for (int k0 = 0; k0 < so; k0 += 64) {
        for (int idx = t; idx < 64 * 64; idx += 512) {
            int rr = idx >> 6, kk = idx & 63;
            Gs[rr][kk] = (rr < nn && k0 + kk < so) ? g_G[b][so + rr][k0 + kk] : 0.f;
            int j = idx & 63, k2 = idx >> 6;
            Ts[k2][j] = (k0 + k2 < so) ? g_T1[b][k0 + k2][j] : 0.f;
        }
        __syncthreads();
        #pragma unroll 8
        for (int k = 0; k < 64; k++) {
            float gv = Gs[i][k];
            #pragma unroll
            for (int jj = 0; jj < 8; jj++) accs[jj] = fmaf(gv, Ts[k][jg * 8 + jj], accs[jj]);
        }
        __syncthreads();
    }
    #pragma unroll
    for (int jj = 0; jj < 8; jj++) {
        int j = jg * 8 + jj;
        float v;
        if (i < nn && j < nn) v = g_G[b][so + i][so + j] - accs[jj];
        else v = (i == j) ? 1.f : 0.f;
        Gs[i][j] = v;
    }
    __syncthreads();
    int row = t >> 3, cg = t & 7;
    float a[16];
    #pragma unroll
    for (int cc = 0; cc < 16; cc++) {
        int c = cg * 16 + cc;
        a[cc] = (c < 64) ? Gs[row][c] : ((c - 64 == row) ? 1.f : 0.f);
    }
    __syncthreads();
    for (int j = 0; j < 64; j++) {
        if (row == j && cg == (j >> 4)) sh_piv = a[j & 15];
        __syncthreads();
        float inv = 1.f / sh_piv;
        if (row == j) {
            #pragma unroll
            for (int cc = 0; cc < 16; cc++) { a[cc] *= inv; pivrow[cg * 16 + cc] = a[cc]; }
        }
        if (cg == (j >> 4)) fcol[row] = a[j & 15];
        __syncthreads();
        float f = (row == j) ? 0.f : fcol[row];
        #pragma unroll
        for (int cc = 0; cc < 16; cc++) a[cc] = fmaf(-f, pivrow[cg * 16 + cc], a[cc]);
    }
    __syncthreads();
    #pragma unroll
    for (int cc = 0; cc < 16; cc++) {
        int c = cg * 16 + cc;
        if (c >= 64) {
            int j = c - 64;
            g_Sinv[b][row][j] = a[cc];
            if (row < nn && j < nn) g_H[b][so + row][so + j] = a[cc];
        }
    }
}

// ---------------- fused T2 + H11: T2 tile kept in smem ----------------
// grid (BD, 8), block 256
__global__ void k_T2H11(void) {
    int b = blockIdx.x;
    if (g_done[b]) return;
    int so = g_sold[b], s = g_scount[b], nn = s - so;
    if (nn == 0) return;
    int r0 = blockIdx.y * 64;
    if (r0 >= so) return;
    __shared__ float As[64 * PAD], Bs[64 * PAD];
    int t = threadIdx.x;
    int ty = t >> 4, tx = t & 15;
    // phase A: T2[r][c] = sum_k T1[r][k] * Sinv[c][k]  (Sinv symmetric)
    for (int idx = t; idx < 64 * 64; idx += 256) {
        int rr = idx >> 6, kk = idx & 63;
        As[rr * PAD + kk] = (r0 + rr < so) ? g_T1[b][r0 + rr][kk] : 0.f;
        Bs[rr * PAD + kk] = g_Sinv[b][rr][kk];
    }
    __syncthreads();
    u64_t acc2[4][4] = {};
    MICROKERNEL(As, Bs)
    float t2v[4][4];
    #pragma unroll
    for (int i = 0; i < 4; i++)
        #pragma unroll
        for (int j = 0; j < 4; j++) t2v[i][j] = acc2sum(acc2[i][j]);
    // epilogue: H12 = -T2, H21 = -T2^T
    #pragma unroll
    for (int i = 0; i < 4; i++) {
        int r = r0 + ty * 4 + i; if (r >= so) continue;
        #pragma unroll
        for (int j = 0; j < 4; j++) {
            int cx = tx * 4 + j;
            if (cx < nn) { g_H[b][r][so + cx] = -t2v[i][j]; g_H[b][so + cx][r] = -t2v[i][j]; }
        }
    }
    __syncthreads();
    // store T2 tile into As (rows r, cols k)
    #pragma unroll
    for (int i = 0; i < 4; i++)
        #pragma unroll
        for (int j = 0; j < 4; j++) As[(ty * 4 + i) * PAD + tx * 4 + j] = t2v[i][j];
    __syncthreads();
    // phase B: H11[r][c] += sum_k T2[r][k] * T1[c][k]
    for (int c0 = 0; c0 < so; c0 += 64) {
        for (int idx = t; idx < 64 * 64; idx += 256) {
            int rr = idx >> 6, kk = idx & 63;
            Bs[rr * PAD + kk] = (c0 + rr < so) ? g_T1[b][c0 + rr][kk] : 0.f;
        }
        __syncthreads();
        u64_t accb[4][4] = {};
        {
            u64_t (&acc2)[4][4] = accb;
            MICROKERNEL(As, Bs)
        }
        #pragma unroll
        for (int i = 0; i < 4; i++) {
            int r = r0 + ty * 4 + i; if (r >= so) continue;
            #pragma unroll
            for (int j = 0; j < 4; j++) {
                int c = c0 + tx * 4 + j; if (c >= so) continue;
                g_H[b][r][c] += acc2sum(accb[i][j]);
            }
        }
        __syncthreads();
    }
}

// ---------------- fused solve (+1 refinement) + radix top-32 + residual ----------------
// grid BD, block 512
__global__ void k_solvethresh(const float* __restrict__ meas) {
    int b = blockIdx.x;
    if (g_done[b]) return;
    int s = g_scount[b];
    int t = threadIdx.x;
    int lane = t & 31, wd = t >> 5;
    __shared__ float cs[SMX], sl[SMX], rs[SMX];
    if (t < s) cs[t] = g_c[b][t]; else cs[t] = 0.f;
    __syncthreads();
    float acc = 0.f;
    #pragma unroll 4
    for (int j = 0; j < s; j++) acc = fmaf(g_H[b][j][t], cs[j], acc);   // H symmetric
    sl[t] = acc;
    __syncthreads();
    acc = 0.f;
    #pragma unroll 4
    for (int j = 0; j < s; j++) acc = fmaf(g_G[b][j][t], sl[j], acc);   // G symmetric
    rs[t] = (t < s) ? (cs[t] - acc) : 0.f;
    __syncthreads();
    acc = 0.f;
    #pragma unroll 4
    for (int j = 0; j < s; j++) acc = fmaf(g_H[b][j][t], rs[j], acc);
    float solv = sl[t] + acc;
    // --- radix select top-32 of |solv| over slots < s ---
    __shared__ int hist[256];
    __shared__ unsigned sh_pref; __shared__ int sh_need;
    unsigned key = (t < s) ? __float_as_uint(fabsf(solv)) : 0u;
    unsigned pref = 0; int need = KK;
    for (int shift = 24; shift >= 0; shift -= 8) {
        unsigned mhi = (shift == 24) ? 0u : (0xFFFFFFFFu << (shift + 8));
        if (t < 256) hist[t] = 0;
        __syncthreads();
        if ((key & mhi) == pref) atomicAdd(&hist[(key >> shift) & 255], 1);
        __syncthreads();
        if (t < 32) {
            int base = 255 - 8 * t;
            int cnt[8]; int ssum = 0;
            #pragma unroll
            for (int q = 0; q < 8; q++) { cnt[q] = hist[base - q]; ssum += cnt[q]; }
            int incl = ssum;
            #pragma unroll
            for (int off = 1; off < 32; off <<= 1) {
                int v = __shfl_up_sync(0xffffffffu, incl, off);
                if (t >= off) incl += v;
            }
            int excl = incl - ssum;
            if (excl < need && need <= incl) {
                int cum = excl;
                #pragma unroll
                for (int q = 0; q < 8; q++) {
                    cum += cnt[q];
                    if (cum >= need) {
                        sh_pref = pref | ((unsigned)(base - q) << shift);
                        sh_need = need - (cum - cnt[q]);
                        break;
                    }
                }
            }
        }
        __syncthreads();
        pref = sh_pref; need = sh_need;
        __syncthreads();
    }
    unsigned T = pref;
    // --- tie resolution by smallest column id ---
    __shared__ int eqsl[SMX]; __shared__ int neq;
    __shared__ unsigned char self_[SMX];
    bool isgt = (key > T) && (t < s);
    bool iseq = (key == T) && (t < s);
    self_[t] = isgt ? 1 : 0;
    if (t == 0) neq = 0;
    __syncthreads();
    if (iseq) { int p = atomicAdd(&neq, 1); eqsl[p] = t; }
    __syncthreads();
    if (t == 0) {
        for (int r = 0; r < need; r++) {
            int bestc = 0x7fffffff, bi = -1;
            for (int q = 0; q < neq; q++) {
                int slot = eqsl[q];
                if (!self_[slot]) { int c = g_suplist[b][slot]; if (c < bestc) { bestc = c; bi = slot; } }
            }
            if (bi >= 0) self_[bi] = 1;
        }
    }
    __syncthreads();
    // --- gather selected 32 in slot order ---
    __shared__ int wsum[16]; __shared__ float pv[KK]; __shared__ int pp[KK];
    __shared__ float rn[16];
    bool sel = self_[t] != 0;
    unsigned bsel = __ballot_sync(0xffffffffu, sel);
    if (lane == 0) wsum[wd] = __popc(bsel);
    __syncthreads();
    int pre = 0;
    #pragma unroll
    for (int w = 0; w < 16; w++) if (w < wd) pre += wsum[w];
    int rank = pre + __popc(bsel & ((1u << lane) - 1));
    if (sel) { pp[rank] = t; pv[rank] = solv; }
    __syncthreads();
    if (t < KK) { g_xcols[b][t] = g_suplist[b][pp[t]]; g_xvals[b][t] = pv[t]; }
    // --- residual update + norm ---
    float nrm = 0.f;
    for (int m = t; m < MD; m += 512) {
        float r = meas[(size_t)b * MD + m];
        #pragma unroll
        for (int j = 0; j < KK; j++) r = fmaf(-pv[j], g_P[b][pp[j]][m], r);
        g_rT[m][b] = r;
        nrm = fmaf(r, r, nrm);
    }
    #pragma unroll
    for (int off = 16; off; off >>= 1) nrm += __shfl_down_sync(0xffffffffu, nrm, off);
    if (lane == 0) rn[wd] = nrm;
    __syncthreads();
    if (t == 0) {
        float tot = 0.f;
        #pragma unroll
        for (int w = 0; w < 16; w++) tot += rn[w];
        if (tot < TOLSQ) g_done[b] = 1;
    }
}

// ---------------- output: zero + scatter ----------------
__global__ void k_out(float* __restrict__ out) {
    int b = blockIdx.x, t = threadIdx.x;
    for (int n = t; n < ND; n += 512) out[(size_t)b * ND + n] = 0.f;
    __syncthreads();
    if (t < KK) out[(size_t)b * ND + g_xcols[b][t]] = g_xvals[b][t];
}

extern "C" void kernel_launch(void* const* d_in, const int* in_sizes, int n_in,
                              void* d_out, int out_size) {
    const float* meas = (const float*)d_in[0];
    const float* A    = (const float*)d_in[1];
    if (n_in >= 2 && in_sizes[0] != BD * MD) {
        meas = (const float*)d_in[1];
        A    = (const float*)d_in[0];
    }
    float* out = (float*)d_out;

    k_transpose<<<dim3(ND / 32, MD / 32), dim3(32, 8)>>>(A);
    k_init<<<256, 256>>>(meas);
    for (int it = 0; it < NITER; it++) {
        k_proxy<<<dim3(4, 4, MSPLIT), 256>>>(A);
        k_topk<<<BD, 512>>>();
        k_pack<<<dim3(BD, KK2), 128>>>(meas);
        k_gram<<<dim3(BD, 8), 256>>>();
        k_T1<<<dim3(BD, 8), 256>>>();
        k_SSinv<<<BD, 512>>>();
        k_T2H11<<<dim3(BD, 8), 256>>>();
        k_solvethresh<<<BD, 512>>>(meas);
    }
    k_out<<<BD, 512>>>(out);
}

// round 6
// speedup vs baseline: 1.6573x; 1.6573x over previous
#include <cuda_runtime.h>
#include <math.h>

#define MD 1024
#define ND 4096
#define BD 16
#define KK 32
#define KK2 64
#define SMX 512
#define NITER 8
#define MSPLIT 8
#define TOLSQ (1e-6f * 1e-6f)
#define PAD 68   // floats per smem row: 16B-aligned (mult of 4); strided mapping keeps LDS.128 conflict-free

typedef unsigned long long u64_t;
__device__ __forceinline__ void fma2(u64_t &d, u64_t a, u64_t b) {
    asm("fma.rn.f32x2 %0, %1, %2, %0;" : "+l"(d) : "l"(a), "l"(b));
}
__device__ __forceinline__ float acc2sum(u64_t v) {
    float lo, hi; asm("mov.b64 {%0,%1}, %2;" : "=f"(lo), "=f"(hi) : "l"(v)); return lo + hi;
}

// ---------------- persistent device state ----------------
__device__ __align__(16) float g_AT[ND][MD];                 // A transposed
__device__ __align__(16) float g_rT[MD][BD];                 // residual transposed [m][b]
__device__ __align__(16) float g_partial[MSPLIT][BD][ND];    // proxy partial sums
__device__ unsigned char g_support[BD][ND];
__device__ int   g_suplist[BD][SMX];
__device__ int   g_scount[BD];
__device__ int   g_sold[BD];
__device__ int   g_done[BD];
__device__ __align__(16) float g_P[BD][SMX][MD];             // packed support columns
__device__ __align__(16) float g_G[BD][SMX][SMX];            // Gram (insertion order)
__device__ __align__(16) float g_H[BD][SMX][SMX];            // running inverse of G
__device__ float g_c[BD][SMX];                               // A_sub^T y
__device__ __align__(16) float g_T1[BD][SMX][KK2];           // H*G12 (pad cols zeroed)
__device__ float g_Sinv[BD][KK2][KK2];                       // padded-identity inverse
__device__ int   g_xcols[BD][KK];
__device__ float g_xvals[BD][KK];

// ---------------- one-time: transpose A ----------------
__global__ void k_transpose(const float* __restrict__ A) {
    __shared__ float tile[32][33];
    int nb = blockIdx.x * 32, mb = blockIdx.y * 32;
    int tx = threadIdx.x, ty = threadIdx.y;
    for (int i = ty; i < 32; i += 8)
        tile[i][tx] = A[(size_t)(mb + i) * ND + nb + tx];
    __syncthreads();
    for (int i = ty; i < 32; i += 8)
        g_AT[nb + i][mb + tx] = tile[tx][i];
}

// ---------------- init ----------------
__global__ void k_init(const float* __restrict__ meas) {
    int i = blockIdx.x * blockDim.x + threadIdx.x;
    int stride = gridDim.x * blockDim.x;
    for (int t = i; t < BD * ND; t += stride) g_support[t / ND][t % ND] = 0;
    if (i < BD * MD) { int b = i / MD, m = i % MD; g_rT[m][b] = meas[b * MD + m]; }
    if (i < BD) { g_scount[i] = 0; g_sold[i] = 0; g_done[i] = 0; }
}

// ---------------- proxy = A^T r, m-split partials ----------------
// grid (4, 4, MSPLIT), block 256
__global__ void k_proxy(const float* __restrict__ A) {
    int t  = threadIdx.x;
    int n0 = (blockIdx.x * 256 + t) * 4;
    int bg = blockIdx.y * 4;
    int mz = blockIdx.z;
    int m0 = mz * (MD / MSPLIT);
    float acc[4][4] = {};
    #pragma unroll 4
    for (int mm = 0; mm < MD / MSPLIT; mm++) {
        int m = m0 + mm;
        float4 a  = *(const float4*)(A + (size_t)m * ND + n0);
        float4 rv = *(const float4*)(&g_rT[m][bg]);
        acc[0][0] = fmaf(a.x, rv.x, acc[0][0]); acc[0][1] = fmaf(a.y, rv.x, acc[0][1]);
        acc[0][2] = fmaf(a.z, rv.x, acc[0][2]); acc[0][3] = fmaf(a.w, rv.x, acc[0][3]);
        acc[1][0] = fmaf(a.x, rv.y, acc[1][0]); acc[1][1] = fmaf(a.y, rv.y, acc[1][1]);
        acc[1][2] = fmaf(a.z, rv.y, acc[1][2]); acc[1][3] = fmaf(a.w, rv.y, acc[1][3]);
        acc[2][0] = fmaf(a.x, rv.z, acc[2][0]); acc[2][1] = fmaf(a.y, rv.z, acc[2][1]);
        acc[2][2] = fmaf(a.z, rv.z, acc[2][2]); acc[2][3] = fmaf(a.w, rv.z, acc[2][3]);
        acc[3][0] = fmaf(a.x, rv.w, acc[3][0]); acc[3][1] = fmaf(a.y, rv.w, acc[3][1]);
        acc[3][2] = fmaf(a.z, rv.w, acc[3][2]); acc[3][3] = fmaf(a.w, rv.w, acc[3][3]);
    }
    #pragma unroll
    for (int bb = 0; bb < 4; bb++) {
        float4 v = make_float4(acc[bb][0], acc[bb][1], acc[bb][2], acc[bb][3]);
        *(float4*)(&g_partial[mz][bg + bb][n0]) = v;
    }
}

// ---------------- radix-select top-64 + support update + FUSED pack ----------------
// grid BD, block 512
__global__ void k_topk(const float* __restrict__ meas) {
    const int BT = 512;
    int b = blockIdx.x;
    if (g_done[b]) return;
    __shared__ unsigned keys[ND];
    __shared__ int hist[4][256];
    __shared__ unsigned sh_pref; __shared__ int sh_need;
    __shared__ int eqlist[128];
    __shared__ int sh_neq, sh_app, sh_sold;
    int t = threadIdx.x;
    int lane = t & 31, wd = t >> 5;
    for (int n = t; n < ND; n += BT) {
        float s = 0.f;
        #pragma unroll
        for (int ms = 0; ms < MSPLIT; ms++) s += g_partial[ms][b][n];
        keys[n] = __float_as_uint(fabsf(s));
    }
    if (t == 0) { sh_sold = g_scount[b]; sh_app = sh_sold; sh_neq = 0; }
    __syncthreads();
    unsigned pref = 0; int need = 2 * KK;
    for (int shift = 24; shift >= 0; shift -= 8) {
        unsigned mhi = (shift == 24) ? 0u : (0xFFFFFFFFu << (shift + 8));
        for (int i = t; i < 1024; i += BT) hist[i >> 8][i & 255] = 0;
        __syncthreads();
        int hs = wd & 3;
        for (int n = t; n < ND; n += BT) {
            unsigned k = keys[n];
            if ((k & mhi) == pref) atomicAdd(&hist[hs][(k >> shift) & 255], 1);
        }
        __syncthreads();
        if (t < 256) hist[0][t] += hist[1][t] + hist[2][t] + hist[3][t];
        __syncthreads();
        if (t < 32) {
            int base = 255 - 8 * t;
            int cnt[8]; int ssum = 0;
            #pragma unroll
            for (int q = 0; q < 8; q++) { cnt[q] = hist[0][base - q]; ssum += cnt[q]; }
            int incl = ssum;
            #pragma unroll
            for (int off = 1; off < 32; off <<= 1) {
                int v = __shfl_up_sync(0xffffffffu, incl, off);
                if (t >= off) incl += v;
            }
            int excl = incl - ssum;
            if (excl < need && need <= incl) {
                int cum = excl;
                #pragma unroll
                for (int q = 0; q < 8; q++) {
                    cum += cnt[q];
                    if (cum >= need) {
                        sh_pref = pref | ((unsigned)(base - q) << shift);
                        sh_need = need - (cum - cnt[q]);
                        break;
                    }
                }
            }
        }
        __syncthreads();
        pref = sh_pref; need = sh_need;
        __syncthreads();
    }
    unsigned T = pref;
    for (int n = t; n < ND; n += BT) {
        unsigned k = keys[n];
        if (k > T) {
            if (!g_support[b][n]) {
                g_support[b][n] = 1;
                int p = atomicAdd(&sh_app, 1);
                g_suplist[b][p] = n;
            }
        } else if (k == T) {
            int q = atomicAdd(&sh_neq, 1);
            if (q < 128) eqlist[q] = n;
        }
    }
    __syncthreads();
    if (t == 0) {
        int ne = sh_neq < 128 ? sh_neq : 128;
        for (int r = 0; r < need; r++) {           // jax ties: smallest index first
            int best = 0x7fffffff, bi = -1;
            for (int q = 0; q < ne; q++) {
                int n = eqlist[q];
                if (n >= 0 && n < best) { best = n; bi = q; }
            }
            if (bi < 0) break;
            eqlist[bi] = -1;
            if (!g_support[b][best]) {
                g_support[b][best] = 1;
                g_suplist[b][sh_app++] = best;
            }
        }
        g_sold[b] = sh_sold;
        g_scount[b] = sh_app;
    }
    __syncthreads();
    // ---- fused pack: copy new columns + c = P_new^T y (warp per column) ----
    int so = sh_sold, s = sh_app, nn = s - so;
    const float4* Y = (const float4*)(meas + (size_t)b * MD);
    for (int p = wd; p < nn; p += 16) {
        int col = g_suplist[b][so + p];
        const float4* Ac = (const float4*)g_AT[col];
        float4* Pd = (float4*)g_P[b][so + p];
        float acc = 0.f;
        #pragma unroll
        for (int i0 = 0; i0 < 256; i0 += 32) {
            int i = i0 + lane;
            float4 v = Ac[i]; float4 yv = Y[i];
            Pd[i] = v;
            acc = fmaf(v.x, yv.x, fmaf(v.y, yv.y, fmaf(v.z, yv.z, fmaf(v.w, yv.w, acc))));
        }
        #pragma unroll
        for (int off = 16; off; off >>= 1) acc += __shfl_down_sync(0xffffffffu, acc, off);
        if (lane == 0) g_c[b][so + p] = acc;
    }
}

// ======== 64x64 microkernel: strided mapping (rows ty+16i, cols tx+16j) ========
// conflict-free LDS.128: adjacent lanes read adjacent PAD-strided rows (17 mod 8 = 1)
#define MICROKERNEL(ASRC, BSRC)                                               \
    {                                                                         \
        _Pragma("unroll")                                                     \
        for (int k4 = 0; k4 < 16; k4++) {                                     \
            ulonglong2 rv[4], cv[4];                                          \
            _Pragma("unroll")                                                 \
            for (int i = 0; i < 4; i++)                                       \
                rv[i] = *(const ulonglong2*)&ASRC[(ty + 16 * i) * PAD + k4 * 4]; \
            _Pragma("unroll")                                                 \
            for (int j = 0; j < 4; j++)                                       \
                cv[j] = *(const ulonglong2*)&BSRC[(tx + 16 * j) * PAD + k4 * 4]; \
            _Pragma("unroll")                                                 \
            for (int i = 0; i < 4; i++)                                       \
                _Pragma("unroll")                                             \
                for (int j = 0; j < 4; j++) {                                 \
                    fma2(acc2[i][j], rv[i].x, cv[j].x);                       \
                    fma2(acc2[i][j], rv[i].y, cv[j].y);                       \
                }                                                             \
        }                                                                     \
    }

// ---------------- Gram new rows: G[so+r][c] = Pnew @ Pall^T ----------------
// grid (BD, 8), block 256
__global__ void k_gram(void) {
    int b = blockIdx.x;
    if (g_done[b]) return;
    int so = g_sold[b], s = g_scount[b], nn = s - so;
    if (nn == 0) return;
    int c0 = blockIdx.y * 64;
    if (c0 >= s) return;
    __shared__ float As[64 * PAD], Bs[64 * PAD];
    int t = threadIdx.x;
    int ty = t >> 4, tx = t & 15;
    u64_t acc2[4][4] = {};
    for (int k0 = 0; k0 < MD; k0 += 64) {
        for (int idx = t; idx < 64 * 64; idx += 256) {
            int rr = idx >> 6, kk = idx & 63;
            As[rr * PAD + kk] = (rr < nn) ? g_P[b][so + rr][k0 + kk] : 0.f;
            Bs[rr * PAD + kk] = (c0 + rr < s) ? g_P[b][c0 + rr][k0 + kk] : 0.f;
        }
        __syncthreads();
        MICROKERNEL(As, Bs)
        __syncthreads();
    }
    #pragma unroll
    for (int i = 0; i < 4; i++) {
        int r = ty + 16 * i; if (r >= nn) continue;
        #pragma unroll
        for (int j = 0; j < 4; j++) {
            int c = c0 + tx + 16 * j; if (c >= s) continue;
            float v = acc2sum(acc2[i][j]);
            g_G[b][so + r][c] = v;
            g_G[b][c][so + r] = v;
        }
    }
}

// ---------------- T1^T formulation: acc[c][r] = sum_k G[so+c][k] * H[r][k] ----------------
// writes g_T1[r][c] (pad cols zeroed).  grid (BD, 8), block 256
__global__ void k_T1(void) {
    int b = blockIdx.x;
    if (g_done[b]) return;
    int so = g_sold[b], s = g_scount[b], nn = s - so;
    if (nn == 0) return;
    int r0 = blockIdx.y * 64;
    if (r0 >= so) return;
    __shared__ float As[64 * PAD], Bs[64 * PAD];
    int t = threadIdx.x;
    int ty = t >> 4, tx = t & 15;
    u64_t acc2[4][4] = {};
    for (int k0 = 0; k0 < so; k0 += 64) {
        for (int idx = t; idx < 64 * 64; idx += 256) {
            int rr = idx >> 6, kk = idx & 63;
            As[rr * PAD + kk] = (rr < nn && k0 + kk < so) ? g_G[b][so + rr][k0 + kk] : 0.f;
            Bs[rr * PAD + kk] = (r0 + rr < so && k0 + kk < so) ? g_H[b][r0 + rr][k0 + kk] : 0.f;
        }
        __syncthreads();
        MICROKERNEL(As, Bs)
        __syncthreads();
    }
    #pragma unroll
    for (int i = 0; i < 4; i++) {
        int c = ty + 16 * i;
        #pragma unroll
        for (int j = 0; j < 4; j++) {
            int r = r0 + tx + 16 * j;
            if (r < so) g_T1[b][r][c] = acc2sum(acc2[i][j]);  // c>=nn slots get 0 (As pad)
        }
    }
}

// ---------------- fused: S = G22 - G21 T1 (smem) -> GJ inverse -> Sinv, H22 ----------------
// grid BD, block 512
__global__ void k_SSinv(void) {
    int b = blockIdx.x;
    if (g_done[b]) return;
    int so = g_sold[b], s = g_scount[b], nn = s - so;
    if (nn == 0) return;
    __shared__ float Gs[64][65], Ts[64][65];
    __shared__ float pivrow[128], fcol[64], sh_piv;
    int t = threadIdx.x;
    int i = t >> 3, jg = t & 7;
    float accs[8] = {};
    for (int k0 = 0; k0 < so; k0 += 64) {
        for (int idx = t; idx < 64 * 64; idx += 512) {
            int rr = idx >> 6, kk = idx & 63;
            Gs[rr][kk] = (rr < nn && k0 + kk < so) ? g_G[b][so + rr][k0 + kk] : 0.f;
            int j = idx & 63, k2 = idx >> 6;
            Ts[k2][j] = (k0 + k2 < so) ? g_T1[b][k0 + k2][j] : 0.f;
        }
        __syncthreads();
        #pragma unroll 8
        for (int k = 0; k < 64; k++) {
            float gv = Gs[i][k];
            #pragma unroll
            for (int jj = 0; jj < 8; jj++) accs[jj] = fmaf(gv, Ts[k][jg * 8 + jj], accs[jj]);
        }
        __syncthreads();
    }
    #pragma unroll
    for (int jj = 0; jj < 8; jj++) {
        int j = jg * 8 + jj;
        float v;
        if (i < nn && j < nn) v = g_G[b][so + i][so + j] - accs[jj];
        else v = (i == j) ? 1.f : 0.f;
        Gs[i][j] = v;
    }
    __syncthreads();
    int row = t >> 3, cg = t & 7;
    float a[16];
    #pragma unroll
    for (int cc = 0; cc < 16; cc++) {
        int c = cg * 16 + cc;
        a[cc] = (c < 64) ? Gs[row][c] : ((c - 64 == row) ? 1.f : 0.f);
    }
    __syncthreads();
    for (int j = 0; j < 64; j++) {
        if (row == j && cg == (j >> 4)) sh_piv = a[j & 15];
        __syncthreads();
        float inv = 1.f / sh_piv;
        if (row == j) {
            #pragma unroll
            for (int cc = 0; cc < 16; cc++) { a[cc] *= inv; pivrow[cg * 16 + cc] = a[cc]; }
        }
        if (cg == (j >> 4)) fcol[row] = a[j & 15];
        __syncthreads();
        float f = (row == j) ? 0.f : fcol[row];
        #pragma unroll
        for (int cc = 0; cc < 16; cc++) a[cc] = fmaf(-f, pivrow[cg * 16 + cc], a[cc]);
    }
    __syncthreads();
    #pragma unroll
    for (int cc = 0; cc < 16; cc++) {
        int c = cg * 16 + cc;
        if (c >= 64) {
            int j = c - 64;
            g_Sinv[b][row][j] = a[cc];
            if (row < nn && j < nn) g_H[b][so + row][so + j] = a[cc];
        }
    }
}

// ---------------- fused T2 + H11 ----------------
// grid (BD, 8), block 256
__global__ void k_T2H11(void) {
    int b = blockIdx.x;
    if (g_done[b]) return;
    int so = g_sold[b], s = g_scount[b], nn = s - so;
    if (nn == 0) return;
    int r0 = blockIdx.y * 64;
    if (r0 >= so) return;
    __shared__ float As[64 * PAD], Bs[64 * PAD];
    int t = threadIdx.x;
    int ty = t >> 4, tx = t & 15;
    // phase A: T2[r][c] = sum_k T1[r][k] * Sinv[c][k]  (Sinv symmetric)
    for (int idx = t; idx < 64 * 64; idx += 256) {
        int rr = idx >> 6, kk = idx & 63;
        As[rr * PAD + kk] = (r0 + rr < so) ? g_T1[b][r0 + rr][kk] : 0.f;
        Bs[rr * PAD + kk] = g_Sinv[b][rr][kk];
    }
    __syncthreads();
    u64_t acc2[4][4] = {};
    MICROKERNEL(As, Bs)
    float t2v[4][4];
    #pragma unroll
    for (int i = 0; i < 4; i++)
        #pragma unroll
        for (int j = 0; j < 4; j++) t2v[i][j] = acc2sum(acc2[i][j]);
    // epilogue: H12 = -T2, H21 = -T2^T
    #pragma unroll
    for (int i = 0; i < 4; i++) {
        int r = r0 + ty + 16 * i; if (r >= so) continue;
        #pragma unroll
        for (int j = 0; j < 4; j++) {
            int cx = tx + 16 * j;
            if (cx < nn) { g_H[b][r][so + cx] = -t2v[i][j]; g_H[b][so + cx][r] = -t2v[i][j]; }
        }
    }
    __syncthreads();
    // store T2 tile into As: local row = ty+16i, k-col = tx+16j
    #pragma unroll
    for (int i = 0; i < 4; i++)
        #pragma unroll
        for (int j = 0; j < 4; j++) As[(ty + 16 * i) * PAD + tx + 16 * j] = t2v[i][j];
    __syncthreads();
    // phase B: H11[r][c] += sum_k T2[r][k] * T1[c][k]
    for (int c0 = 0; c0 < so; c0 += 64) {
        for (int idx = t; idx < 64 * 64; idx += 256) {
            int rr = idx >> 6, kk = idx & 63;
            Bs[rr * PAD + kk] = (c0 + rr < so) ? g_T1[b][c0 + rr][kk] : 0.f;
        }
        __syncthreads();
        u64_t accb[4][4] = {};
        {
            u64_t (&acc2)[4][4] = accb;
            MICROKERNEL(As, Bs)
        }
        #pragma unroll
        for (int i = 0; i < 4; i++) {
            int r = r0 + ty + 16 * i; if (r >= so) continue;
            #pragma unroll
            for (int j = 0; j < 4; j++) {
                int c = c0 + tx + 16 * j; if (c >= so) continue;
                g_H[b][r][c] += acc2sum(accb[i][j]);
            }
        }
        __syncthreads();
    }
}

// high-MLP matvec: acc over j<spad of W[j][t]*v[j] (v zero-padded)
#define MATVEC16(W, VEC, OUTVAR)                                   \
    {                                                              \
        float a0 = 0.f, a1 = 0.f, a2 = 0.f, a3 = 0.f;              \
        for (int j0 = 0; j0 < spad; j0 += 16) {                    \
            _Pragma("unroll")                                      \
            for (int jj = 0; jj < 16; jj += 4) {                   \
                a0 = fmaf(W[b][j0 + jj + 0][t], VEC[j0 + jj + 0], a0); \
                a1 = fmaf(W[b][j0 + jj + 1][t], VEC[j0 + jj + 1], a1); \
                a2 = fmaf(W[b][j0 + jj + 2][t], VEC[j0 + jj + 2], a2); \
                a3 = fmaf(W[b][j0 + jj + 3][t], VEC[j0 + jj + 3], a3); \
            }                                                      \
        }                                                          \
        OUTVAR = ((a0 + a1) + (a2 + a3));                          \
    }

// ---------------- fused solve (+1 refinement) + radix top-32 + residual ----------------
// grid BD, block 512
__global__ void k_solvethresh(const float* __restrict__ meas) {
    int b = blockIdx.x;
    if (g_done[b]) return;
    int s = g_scount[b];
    int spad = (s + 15) & ~15;
    int t = threadIdx.x;
    int lane = t & 31, wd = t >> 5;
    __shared__ float cs[SMX], sl[SMX], rs[SMX];
    cs[t] = (t < s) ? g_c[b][t] : 0.f;
    __syncthreads();
    float v0;
    MATVEC16(g_H, cs, v0)            // sl = H c (H symmetric; stale rows * 0 = 0)
    sl[t] = (t < s) ? v0 : 0.f;
    __syncthreads();
    float v1;
    MATVEC16(g_G, sl, v1)            // G sol (G symmetric)
    rs[t] = (t < s) ? (cs[t] - v1) : 0.f;
    __syncthreads();
    float v2;
    MATVEC16(g_H, rs, v2)            // refinement
    float solv = (t < s) ? (sl[t] + v2) : 0.f;
    // --- radix select top-32 of |solv| over slots < s ---
    __shared__ int hist[256];
    __shared__ unsigned sh_pref; __shared__ int sh_need;
    unsigned key = (t < s) ? __float_as_uint(fabsf(solv)) : 0u;
    unsigned pref = 0; int need = KK;
    for (int shift = 24; shift >= 0; shift -= 8) {
        unsigned mhi = (shift == 24) ? 0u : (0xFFFFFFFFu << (shift + 8));
        if (t < 256) hist[t] = 0;
        __syncthreads();
        if ((key & mhi) == pref) atomicAdd(&hist[(key >> shift) & 255], 1);
        __syncthreads();
        if (t < 32) {
            int base = 255 - 8 * t;
            int cnt[8]; int ssum = 0;
            #pragma unroll
            for (int q = 0; q < 8; q++) { cnt[q] = hist[base - q]; ssum += cnt[q]; }
            int incl = ssum;
            #pragma unroll
            for (int off = 1; off < 32; off <<= 1) {
                int v = __shfl_up_sync(0xffffffffu, incl, off);
                if (t >= off) incl += v;
            }
            int excl = incl - ssum;
            if (excl < need && need <= incl) {
                int cum = excl;
                #pragma unroll
                for (int q = 0; q < 8; q++) {
                    cum += cnt[q];
                    if (cum >= need) {
                        sh_pref = pref | ((unsigned)(base - q) << shift);
                        sh_need = need - (cum - cnt[q]);
                        break;
                    }
                }
            }
        }
        __syncthreads();
        pref = sh_pref; need = sh_need;
        __syncthreads();
    }
    unsigned T = pref;
    // --- tie resolution by smallest column id ---
    __shared__ int eqsl[SMX]; __shared__ int neq;
    __shared__ unsigned char self_[SMX];
    bool isgt = (key > T) && (t < s);
    bool iseq = (key == T) && (t < s);
    self_[t] = isgt ? 1 : 0;
    if (t == 0) neq = 0;
    __syncthreads();
    if (iseq) { int p = atomicAdd(&neq, 1); eqsl[p] = t; }
    __syncthreads();
    if (t == 0) {
        for (int r = 0; r < need; r++) {
            int bestc = 0x7fffffff, bi = -1;
            for (int q = 0; q < neq; q++) {
                int slot = eqsl[q];
                if (!self_[slot]) { int c = g_suplist[b][slot]; if (c < bestc) { bestc = c; bi = slot; } }
            }
            if (bi >= 0) self_[bi] = 1;
        }
    }
    __syncthreads();
    // --- gather selected 32 in slot order ---
    __shared__ int wsum[16]; __shared__ float pv[KK]; __shared__ int pp[KK];
    __shared__ float rn[16];
    bool sel = self_[t] != 0;
    unsigned bsel = __ballot_sync(0xffffffffu, sel);
    if (lane == 0) wsum[wd] = __popc(bsel);
    __syncthreads();
    int pre = 0;
    #pragma unroll
    for (int w = 0; w < 16; w++) if (w < wd) pre += wsum[w];
    int rank = pre + __popc(bsel & ((1u << lane) - 1));
    if (sel) { pp[rank] = t; pv[rank] = solv; }
    __syncthreads();
    if (t < KK) { g_xcols[b][t] = g_suplist[b][pp[t]]; g_xvals[b][t] = pv[t]; }
    // --- residual update + norm ---
    float nrm = 0.f;
    for (int m = t; m < MD; m += 512) {
        float r = meas[(size_t)b * MD + m];
        #pragma unroll
        for (int j = 0; j < KK; j++) r = fmaf(-pv[j], g_P[b][pp[j]][m], r);
        g_rT[m][b] = r;
        nrm = fmaf(r, r, nrm);
    }
    #pragma unroll
    for (int off = 16; off; off >>= 1) nrm += __shfl_down_sync(0xffffffffu, nrm, off);
    if (lane == 0) rn[wd] = nrm;
    __syncthreads();
    if (t == 0) {
        float tot = 0.f;
        #pragma unroll
        for (int w = 0; w < 16; w++) tot += rn[w];
        if (tot < TOLSQ) g_done[b] = 1;
    }
}

// ---------------- output: zero + scatter ----------------
__global__ void k_out(float* __restrict__ out) {
    int b = blockIdx.x, t = threadIdx.x;
    for (int n = t; n < ND; n += 512) out[(size_t)b * ND + n] = 0.f;
    __syncthreads();
    if (t < KK) out[(size_t)b * ND + g_xcols[b][t]] = g_xvals[b][t];
}

extern "C" void kernel_launch(void* const* d_in, const int* in_sizes, int n_in,
                              void* d_out, int out_size) {
    const float* meas = (const float*)d_in[0];
    const float* A    = (const float*)d_in[1];
    if (n_in >= 2 && in_sizes[0] != BD * MD) {
        meas = (const float*)d_in[1];
        A    = (const float*)d_in[0];
    }
    float* out = (float*)d_out;

    k_transpose<<<dim3(ND / 32, MD / 32), dim3(32, 8)>>>(A);
    k_init<<<256, 256>>>(meas);
    for (int it = 0; it < NITER; it++) {
        k_proxy<<<dim3(4, 4, MSPLIT), 256>>>(A);
        k_topk<<<BD, 512>>>(meas);
        k_gram<<<dim3(BD, 8), 256>>>();
        k_T1<<<dim3(BD, 8), 256>>>();
        k_SSinv<<<BD, 512>>>();
        k_T2H11<<<dim3(BD, 8), 256>>>();
        k_solvethresh<<<BD, 512>>>(meas);
    }
    k_out<<<BD, 512>>>(out);
}

// round 7
// speedup vs baseline: 2.2114x; 1.3343x over previous
#include <cuda_runtime.h>
#include <math.h>

#define MD 1024
#define ND 4096
#define BD 16
#define KK 32
#define KK2 64
#define SMX 512
#define NITER 8
#define MSPLIT 8
#define TOLSQ (1e-6f * 1e-6f)
#define PAD 68
#define TILE (64 * PAD)   // floats per smem tile

typedef unsigned long long u64_t;
__device__ __forceinline__ void fma2(u64_t &d, u64_t a, u64_t b) {
    asm("fma.rn.f32x2 %0, %1, %2, %0;" : "+l"(d) : "l"(a), "l"(b));
}
__device__ __forceinline__ float acc2sum(u64_t v) {
    float lo, hi; asm("mov.b64 {%0,%1}, %2;" : "=f"(lo), "=f"(hi) : "l"(v)); return lo + hi;
}
__device__ __forceinline__ void cpa16(float* dst, const float* src) {
    unsigned d = (unsigned)__cvta_generic_to_shared(dst);
    asm volatile("cp.async.cg.shared.global [%0], [%1], 16;" :: "r"(d), "l"(src) : "memory");
}
__device__ __forceinline__ void cpcommit() { asm volatile("cp.async.commit_group;" ::: "memory"); }
__device__ __forceinline__ void cpwait0()  { asm volatile("cp.async.wait_group 0;" ::: "memory"); }
__device__ __forceinline__ void cpwait1()  { asm volatile("cp.async.wait_group 1;" ::: "memory"); }

// ---------------- persistent device state ----------------
__device__ __align__(16) float g_AT[ND][MD];
__device__ __align__(16) float g_rT[MD][BD];
__device__ __align__(16) float g_partial[MSPLIT][BD][ND];
__device__ unsigned char g_support[BD][ND];
__device__ int   g_suplist[BD][SMX];
__device__ int   g_scount[BD];
__device__ int   g_sold[BD];
__device__ int   g_done[BD];
__device__ __align__(16) float g_P[BD][SMX][MD];
__device__ __align__(16) float g_G[BD][SMX][SMX];   // zero beyond s (invariant)
__device__ __align__(16) float g_H[BD][SMX][SMX];   // zero beyond s (invariant)
__device__ float g_c[BD][SMX];
__device__ __align__(16) float g_T1[BD][SMX][KK2];  // zero rows >= so (invariant)
__device__ float g_Sinv[BD][KK2][KK2];
__device__ int   g_xcols[BD][KK];
__device__ float g_xvals[BD][KK];

// ---------------- one-time: transpose A ----------------
__global__ void k_transpose(const float* __restrict__ A) {
    __shared__ float tile[32][33];
    int nb = blockIdx.x * 32, mb = blockIdx.y * 32;
    int tx = threadIdx.x, ty = threadIdx.y;
    for (int i = ty; i < 32; i += 8)
        tile[i][tx] = A[(size_t)(mb + i) * ND + nb + tx];
    __syncthreads();
    for (int i = ty; i < 32; i += 8)
        g_AT[nb + i][mb + tx] = tile[tx][i];
}

// ---------------- init: state + zero-invariant for G/H/T1 ----------------
// grid 2048, block 256
__global__ void k_init(const float* __restrict__ meas) {
    long i = (long)blockIdx.x * blockDim.x + threadIdx.x;
    long stride = (long)gridDim.x * blockDim.x;
    float4 z4 = make_float4(0.f, 0.f, 0.f, 0.f);
    long ng = (long)BD * SMX * SMX / 4;
    float4* pg = (float4*)g_G;
    for (long k = i; k < ng; k += stride) pg[k] = z4;
    float4* ph = (float4*)g_H;
    for (long k = i; k < ng; k += stride) ph[k] = z4;
    long nt = (long)BD * SMX * KK2 / 4;
    float4* pt = (float4*)g_T1;
    for (long k = i; k < nt; k += stride) pt[k] = z4;
    for (long k = i; k < (long)BD * ND; k += stride) g_support[k / ND][k % ND] = 0;
    if (i < BD * MD) { int b = (int)(i / MD), m = (int)(i % MD); g_rT[m][b] = meas[b * MD + m]; }
    if (i < BD) { g_scount[i] = 0; g_sold[i] = 0; g_done[i] = 0; }
}

// ---------------- proxy = A^T r, m-split partials ----------------
// grid (4, 4, MSPLIT), block 256
__global__ void k_proxy(const float* __restrict__ A) {
    int t  = threadIdx.x;
    int n0 = (blockIdx.x * 256 + t) * 4;
    int bg = blockIdx.y * 4;
    int mz = blockIdx.z;
    int m0 = mz * (MD / MSPLIT);
    float acc[4][4] = {};
    #pragma unroll 4
    for (int mm = 0; mm < MD / MSPLIT; mm++) {
        int m = m0 + mm;
        float4 a  = *(const float4*)(A + (size_t)m * ND + n0);
        float4 rv = *(const float4*)(&g_rT[m][bg]);
        acc[0][0] = fmaf(a.x, rv.x, acc[0][0]); acc[0][1] = fmaf(a.y, rv.x, acc[0][1]);
        acc[0][2] = fmaf(a.z, rv.x, acc[0][2]); acc[0][3] = fmaf(a.w, rv.x, acc[0][3]);
        acc[1][0] = fmaf(a.x, rv.y, acc[1][0]); acc[1][1] = fmaf(a.y, rv.y, acc[1][1]);
        acc[1][2] = fmaf(a.z, rv.y, acc[1][2]); acc[1][3] = fmaf(a.w, rv.y, acc[1][3]);
        acc[2][0] = fmaf(a.x, rv.z, acc[2][0]); acc[2][1] = fmaf(a.y, rv.z, acc[2][1]);
        acc[2][2] = fmaf(a.z, rv.z, acc[2][2]); acc[2][3] = fmaf(a.w, rv.z, acc[2][3]);
        acc[3][0] = fmaf(a.x, rv.w, acc[3][0]); acc[3][1] = fmaf(a.y, rv.w, acc[3][1]);
        acc[3][2] = fmaf(a.z, rv.w, acc[3][2]); acc[3][3] = fmaf(a.w, rv.w, acc[3][3]);
    }
    #pragma unroll
    for (int bb = 0; bb < 4; bb++) {
        float4 v = make_float4(acc[bb][0], acc[bb][1], acc[bb][2], acc[bb][3]);
        *(float4*)(&g_partial[mz][bg + bb][n0]) = v;
    }
}

// ---------------- radix-select top-64 + support update + fused pack ----------------
// grid BD, block 512
__global__ void k_topk(const float* __restrict__ meas) {
    const int BT = 512;
    int b = blockIdx.x;
    if (g_done[b]) return;
    __shared__ unsigned keys[ND];
    __shared__ float ysh[MD];
    __shared__ int hist[4][256];
    __shared__ unsigned sh_pref; __shared__ int sh_need;
    __shared__ int eqlist[128];
    __shared__ int sh_neq, sh_app, sh_sold;
    int t = threadIdx.x;
    int lane = t & 31, wd = t >> 5;
    for (int n = t; n < ND; n += BT) {
        float s = 0.f;
        #pragma unroll
        for (int ms = 0; ms < MSPLIT; ms++) s += g_partial[ms][b][n];
        keys[n] = __float_as_uint(fabsf(s));
    }
    for (int m = t; m < MD; m += BT) ysh[m] = meas[(size_t)b * MD + m];
    if (t == 0) { sh_sold = g_scount[b]; sh_app = sh_sold; sh_neq = 0; }
    __syncthreads();
    unsigned pref = 0; int need = 2 * KK;
    for (int shift = 24; shift >= 0; shift -= 8) {
        unsigned mhi = (shift == 24) ? 0u : (0xFFFFFFFFu << (shift + 8));
        for (int i = t; i < 1024; i += BT) hist[i >> 8][i & 255] = 0;
        __syncthreads();
        int hs = wd & 3;
        for (int n = t; n < ND; n += BT) {
            unsigned k = keys[n];
            if ((k & mhi) == pref) atomicAdd(&hist[hs][(k >> shift) & 255], 1);
        }
        __syncthreads();
        if (t < 256) hist[0][t] += hist[1][t] + hist[2][t] + hist[3][t];
        __syncthreads();
        if (t < 32) {
            int base = 255 - 8 * t;
            int cnt[8]; int ssum = 0;
            #pragma unroll
            for (int q = 0; q < 8; q++) { cnt[q] = hist[0][base - q]; ssum += cnt[q]; }
            int incl = ssum;
            #pragma unroll
            for (int off = 1; off < 32; off <<= 1) {
                int v = __shfl_up_sync(0xffffffffu, incl, off);
                if (t >= off) incl += v;
            }
            int excl = incl - ssum;
            if (excl < need && need <= incl) {
                int cum = excl;
                #pragma unroll
                for (int q = 0; q < 8; q++) {
                    cum += cnt[q];
                    if (cum >= need) {
                        sh_pref = pref | ((unsigned)(base - q) << shift);
                        sh_need = need - (cum - cnt[q]);
                        break;
                    }
                }
            }
        }
        __syncthreads();
        pref = sh_pref; need = sh_need;
        __syncthreads();
    }
    unsigned T = pref;
    for (int n = t; n < ND; n += BT) {
        unsigned k = keys[n];
        if (k > T) {
            if (!g_support[b][n]) {
                g_support[b][n] = 1;
                int p = atomicAdd(&sh_app, 1);
                g_suplist[b][p] = n;
            }
        } else if (k == T) {
            int q = atomicAdd(&sh_neq, 1);
            if (q < 128) eqlist[q] = n;
        }
    }
    __syncthreads();
    if (t == 0) {
        int ne = sh_neq < 128 ? sh_neq : 128;
        for (int r = 0; r < need; r++) {           // jax ties: smallest index first
            int best = 0x7fffffff, bi = -1;
            for (int q = 0; q < ne; q++) {
                int n = eqlist[q];
                if (n >= 0 && n < best) { best = n; bi = q; }
            }
            if (bi < 0) break;
            eqlist[bi] = -1;
            if (!g_support[b][best]) {
                g_support[b][best] = 1;
                g_suplist[b][sh_app++] = best;
            }
        }
        g_sold[b] = sh_sold;
        g_scount[b] = sh_app;
    }
    __syncthreads();
    // ---- fused pack: high-MLP copy + dot (warp per column) ----
    int so = sh_sold, s = sh_app, nn = s - so;
    for (int p = wd; p < nn; p += 16) {
        int col = g_suplist[b][so + p];
        const float4* Ac = (const float4*)g_AT[col];
        float4* Pd = (float4*)g_P[b][so + p];
        float4 v[8];
        #pragma unroll
        for (int i = 0; i < 8; i++) v[i] = Ac[i * 32 + lane];
        float acc = 0.f;
        #pragma unroll
        for (int i = 0; i < 8; i++) {
            Pd[i * 32 + lane] = v[i];
            const float4 yv = *(const float4*)&ysh[(i * 32 + lane) * 4];
            acc = fmaf(v[i].x, yv.x, fmaf(v[i].y, yv.y, fmaf(v[i].z, yv.z, fmaf(v[i].w, yv.w, acc))));
        }
        #pragma unroll
        for (int off = 16; off; off >>= 1) acc += __shfl_down_sync(0xffffffffu, acc, off);
        if (lane == 0) g_c[b][so + p] = acc;
    }
}

// ======== 64x64 microkernel: strided mapping, conflict-free LDS.128 ========
#define MICROKERNEL(ASRC, BSRC)                                               \
    {                                                                         \
        _Pragma("unroll")                                                     \
        for (int k4 = 0; k4 < 16; k4++) {                                     \
            ulonglong2 rv[4], cv[4];                                          \
            _Pragma("unroll")                                                 \
            for (int i = 0; i < 4; i++)                                       \
                rv[i] = *(const ulonglong2*)&(ASRC)[(ty + 16 * i) * PAD + k4 * 4]; \
            _Pragma("unroll")                                                 \
            for (int j = 0; j < 4; j++)                                       \
                cv[j] = *(const ulonglong2*)&(BSRC)[(tx + 16 * j) * PAD + k4 * 4]; \
            _Pragma("unroll")                                                 \
            for (int i = 0; i < 4; i++)                                       \
                _Pragma("unroll")                                             \
                for (int j = 0; j < 4; j++) {                                 \
                    fma2(acc2[i][j], rv[i].x, cv[j].x);                       \
                    fma2(acc2[i][j], rv[i].y, cv[j].y);                       \
                }                                                             \
        }                                                                     \
    }

// cp.async tile load: 64 rows x 16 float4, 256 threads, 4 per thread per array
#define LOAD2(Ad, Bd, ASRCROW, BSRCROW, K0)                                   \
    {                                                                         \
        _Pragma("unroll")                                                     \
        for (int q = 0; q < 4; q++) {                                         \
            int idx = t + 256 * q;                                            \
            int r = idx >> 4, f = (idx & 15) * 4;                             \
            cpa16(&(Ad)[r * PAD + f], &(ASRCROW)[(K0) + f]);                  \
            cpa16(&(Bd)[r * PAD + f], &(BSRCROW)[(K0) + f]);                  \
        }                                                                     \
        cpcommit();                                                           \
    }

// ---------------- Gram new rows: G[so+r][c] = Pnew @ Pall^T (pipelined) ----------------
// grid (BD, 8), block 256, dyn smem 4*TILE floats
__global__ void k_gram(void) {
    int b = blockIdx.x;
    if (g_done[b]) return;
    int so = g_sold[b], s = g_scount[b], nn = s - so;
    if (nn == 0) return;
    int c0 = blockIdx.y * 64;
    if (c0 >= s) return;
    extern __shared__ float sm[];
    float* Ab = sm;            // 2 tiles
    float* Bb = sm + 2 * TILE; // 2 tiles
    int t = threadIdx.x;
    int ty = t >> 4, tx = t & 15;
    u64_t acc2[4][4] = {};
    {
        #pragma unroll
        for (int q = 0; q < 4; q++) {
            int idx = t + 256 * q; int r = idx >> 4, f = (idx & 15) * 4;
            int ra = so + r; ra = ra < SMX ? ra : SMX - 1;   // clamp (garbage rows never stored)
            cpa16(&Ab[r * PAD + f], &g_P[b][ra][f]);
            cpa16(&Bb[r * PAD + f], &g_P[b][c0 + r][f]);
        }
        cpcommit();
    }
    for (int step = 0; step < 16; step++) {
        int cur = step & 1;
        if (step < 15) {
            float* Ad = Ab + (cur ^ 1) * TILE;
            float* Bd = Bb + (cur ^ 1) * TILE;
            int k0 = (step + 1) * 64;
            #pragma unroll
            for (int q = 0; q < 4; q++) {
                int idx = t + 256 * q; int r = idx >> 4, f = (idx & 15) * 4;
                int ra = so + r; ra = ra < SMX ? ra : SMX - 1;
                cpa16(&Ad[r * PAD + f], &g_P[b][ra][k0 + f]);
                cpa16(&Bd[r * PAD + f], &g_P[b][c0 + r][k0 + f]);
            }
            cpcommit();
            cpwait1();
        } else cpwait0();
        __syncthreads();
        const float* As = Ab + cur * TILE;
        const float* Bs = Bb + cur * TILE;
        MICROKERNEL(As, Bs)
        __syncthreads();
    }
    #pragma unroll
    for (int i = 0; i < 4; i++) {
        int r = ty + 16 * i; if (r >= nn) continue;
        #pragma unroll
        for (int j = 0; j < 4; j++) {
            int c = c0 + tx + 16 * j; if (c >= s) continue;
            float v = acc2sum(acc2[i][j]);
            g_G[b][so + r][c] = v;
            g_G[b][c][so + r] = v;
        }
    }
}

// ---------------- T1: acc[c][r] = sum_k G[so+c][k] H[r][k] (pipelined, guard-free) ----------------
// grid (BD, 8), block 256, dyn smem 4*TILE floats
__global__ void k_T1(void) {
    int b = blockIdx.x;
    if (g_done[b]) return;
    int so = g_sold[b], s = g_scount[b], nn = s - so;
    if (nn == 0) return;
    int r0 = blockIdx.y * 64;
    if (r0 >= so) return;
    extern __shared__ float sm[];
    float* Ab = sm;
    float* Bb = sm + 2 * TILE;
    int t = threadIdx.x;
    int ty = t >> 4, tx = t & 15;
    int NS = (so + 63) >> 6;
    u64_t acc2[4][4] = {};
    {
        #pragma unroll
        for (int q = 0; q < 4; q++) {
            int idx = t + 256 * q; int r = idx >> 4, f = (idx & 15) * 4;
            int ra = so + r; ra = ra < SMX ? ra : SMX - 1;
            cpa16(&Ab[r * PAD + f], &g_G[b][ra][f]);       // rows >= s are zero (invariant)
            cpa16(&Bb[r * PAD + f], &g_H[b][r0 + r][f]);   // rows/cols >= so are zero
        }
        cpcommit();
    }
    for (int step = 0; step < NS; step++) {
        int cur = step & 1;
        if (step + 1 < NS) {
            float* Ad = Ab + (cur ^ 1) * TILE;
            float* Bd = Bb + (cur ^ 1) * TILE;
            int k0 = (step + 1) * 64;
            #pragma unroll
            for (int q = 0; q < 4; q++) {
                int idx = t + 256 * q; int r = idx >> 4, f = (idx & 15) * 4;
                int ra = so + r; ra = ra < SMX ? ra : SMX - 1;
                cpa16(&Ad[r * PAD + f], &g_G[b][ra][k0 + f]);
                cpa16(&Bd[r * PAD + f], &g_H[b][r0 + r][k0 + f]);
            }
            cpcommit();
            cpwait1();
        } else cpwait0();
        __syncthreads();
        const float* As = Ab + cur * TILE;
        const float* Bs = Bb + cur * TILE;
        MICROKERNEL(As, Bs)
        __syncthreads();
    }
    #pragma unroll
    for (int i = 0; i < 4; i++) {
        int c = ty + 16 * i;
        #pragma unroll
        for (int j = 0; j < 4; j++) {
            int r = r0 + tx + 16 * j;
            g_T1[b][r][c] = acc2sum(acc2[i][j]);  // rows >= so store exact 0 (keeps invariant)
        }
    }
}

// ---------------- fused: S = G22 - G21 T1 -> GJ inverse -> Sinv, H22 ----------------
// grid BD, block 512 (guard-free k loops via zero invariant)
__global__ void k_SSinv(void) {
    int b = blockIdx.x;
    if (g_done[b]) return;
    int so = g_sold[b], s = g_scount[b], nn = s - so;
    if (nn == 0) return;
    __shared__ float Gs[64][65], Ts[64][65];
    __shared__ float pivrow[128], fcol[64], sh_piv;
    int t = threadIdx.x;
    int i = t >> 3, jg = t & 7;
    float accs[8] = {};
    for (int k0 = 0; k0 < so; k0 += 64) {
        for (int idx = t; idx < 64 * 64; idx += 512) {
            int rr = idx >> 6, kk = idx & 63;
            int ra = so + rr; ra = ra < SMX ? ra : SMX - 1;
            Gs[rr][kk] = g_G[b][ra][k0 + kk];          // k >= so pairs with zero T1 rows
            int j = idx & 63, k2 = idx >> 6;
            Ts[k2][j] = g_T1[b][k0 + k2][j];           // rows >= so are zero
        }
        __syncthreads();
        #pragma unroll 8
        for (int k = 0; k < 64; k++) {
            float gv = Gs[i][k];
            #pragma unroll
            for (int jj = 0; jj < 8; jj++) accs[jj] = fmaf(gv, Ts[k][jg * 8 + jj], accs[jj]);
        }
        __syncthreads();
    }
    #pragma unroll
    for (int jj = 0; jj < 8; jj++) {
        int j = jg * 8 + jj;
        float v;
        if (i < nn && j < nn) v = g_G[b][so + i][so + j] - accs[jj];
        else v = (i == j) ? 1.f : 0.f;
        Gs[i][j] = v;
    }
    __syncthreads();
    int row = t >> 3, cg = t & 7;
    float a[16];
    #pragma unroll
    for (int cc = 0; cc < 16; cc++) {
        int c = cg * 16 + cc;
        a[cc] = (c < 64) ? Gs[row][c] : ((c - 64 == row) ? 1.f : 0.f);
    }
    __syncthreads();
    for (int j = 0; j < 64; j++) {
        if (row == j && cg == (j >> 4)) sh_piv = a[j & 15];
        __syncthreads();
        float inv = 1.f / sh_piv;
        if (row == j) {
            #pragma unroll
            for (int cc = 0; cc < 16; cc++) { a[cc] *= inv; pivrow[cg * 16 + cc] = a[cc]; }
        }
        if (cg == (j >> 4)) fcol[row] = a[j & 15];
        __syncthreads();
        float f = (row == j) ? 0.f : fcol[row];
        #pragma unroll
        for (int cc = 0; cc < 16; cc++) a[cc] = fmaf(-f, pivrow[cg * 16 + cc], a[cc]);
    }
    __syncthreads();
    #pragma unroll
    for (int cc = 0; cc < 16; cc++) {
        int c = cg * 16 + cc;
        if (c >= 64) {
            int j = c - 64;
            g_Sinv[b][row][j] = a[cc];
            if (row < nn && j < nn) g_H[b][so + row][so + j] = a[cc];
        }
    }
}

// ---------------- fused T2 + H11 (phase B pipelined) ----------------
// grid (BD, 8), block 256, dyn smem 3*TILE floats
__global__ void k_T2H11(void) {
    int b = blockIdx.x;
    if (g_done[b]) return;
    int so = g_sold[b], s = g_scount[b], nn = s - so;
    if (nn == 0) return;
    int r0 = blockIdx.y * 64;
    if (r0 >= so) return;
    extern __shared__ float sm[];
    float* As = sm;            // 1 tile (T1 rows, then T2)
    float* Bb = sm + TILE;     // 2 tiles
    int t = threadIdx.x;
    int ty = t >> 4, tx = t & 15;
    // phase A: T2[r][c] = sum_k T1[r][k] * Sinv[c][k]
    {
        #pragma unroll
        for (int q = 0; q < 4; q++) {
            int idx = t + 256 * q; int r = idx >> 4, f = (idx & 15) * 4;
            cpa16(&As[r * PAD + f], &g_T1[b][r0 + r][f]);
            cpa16(&Bb[r * PAD + f], &g_Sinv[b][r][f]);
        }
        cpcommit(); cpwait0();
    }
    __syncthreads();
    u64_t acc2[4][4] = {};
    MICROKERNEL(As, Bb)
    float t2v[4][4];
    #pragma unroll
    for (int i = 0; i < 4; i++)
        #pragma unroll
        for (int j = 0; j < 4; j++) t2v[i][j] = acc2sum(acc2[i][j]);
    #pragma unroll
    for (int i = 0; i < 4; i++) {
        int r = r0 + ty + 16 * i; if (r >= so) continue;
        #pragma unroll
        for (int j = 0; j < 4; j++) {
            int cx = tx + 16 * j;
            if (cx < nn) { g_H[b][r][so + cx] = -t2v[i][j]; g_H[b][so + cx][r] = -t2v[i][j]; }
        }
    }
    __syncthreads();   // all phase-A reads done
    #pragma unroll
    for (int i = 0; i < 4; i++)
        #pragma unroll
        for (int j = 0; j < 4; j++) As[(ty + 16 * i) * PAD + tx + 16 * j] = t2v[i][j];
    // phase B: H11[r][c] += sum_k T2[r][k] * T1[c][k]  (pipelined over c0)
    int NS = (so + 63) >> 6;
    {
        #pragma unroll
        for (int q = 0; q < 4; q++) {
            int idx = t + 256 * q; int r = idx >> 4, f = (idx & 15) * 4;
            cpa16(&Bb[r * PAD + f], &g_T1[b][r][f]);
        }
        cpcommit();
    }
    for (int step = 0; step < NS; step++) {
        int cur = step & 1;
        if (step + 1 < NS) {
            float* Bd = Bb + (cur ^ 1) * TILE;
            int c0n = (step + 1) * 64;
            #pragma unroll
            for (int q = 0; q < 4; q++) {
                int idx = t + 256 * q; int r = idx >> 4, f = (idx & 15) * 4;
                cpa16(&Bd[r * PAD + f], &g_T1[b][c0n + r][f]);
            }
            cpcommit();
            cpwait1();
        } else cpwait0();
        __syncthreads();
        const float* Bs = Bb + cur * TILE;
        u64_t accb[4][4] = {};
        {
            u64_t (&acc2)[4][4] = accb;
            MICROKERNEL(As, Bs)
        }
        int c0 = step * 64;
        #pragma unroll
        for (int i = 0; i < 4; i++) {
            int r = r0 + ty + 16 * i; if (r >= so) continue;
            #pragma unroll
            for (int j = 0; j < 4; j++) {
                int c = c0 + tx + 16 * j; if (c >= so) continue;
                g_H[b][r][c] += acc2sum(accb[i][j]);
            }
        }
        __syncthreads();
    }
}

// high-MLP matvec over zero-padded rows
#define MATVEC16(W, VEC, OUTVAR)                                   \
    {                                                              \
        float a0 = 0.f, a1 = 0.f, a2 = 0.f, a3 = 0.f;              \
        for (int j0 = 0; j0 < spad; j0 += 16) {                    \
            _Pragma("unroll")                                      \
            for (int jj = 0; jj < 16; jj += 4) {                   \
                a0 = fmaf(W[b][j0 + jj + 0][t], VEC[j0 + jj + 0], a0); \
                a1 = fmaf(W[b][j0 + jj + 1][t], VEC[j0 + jj + 1], a1); \
                a2 = fmaf(W[b][j0 + jj + 2][t], VEC[j0 + jj + 2], a2); \
                a3 = fmaf(W[b][j0 + jj + 3][t], VEC[j0 + jj + 3], a3); \
            }                                                      \
        }                                                          \
        OUTVAR = ((a0 + a1) + (a2 + a3));                          \
    }

// ---------------- fused solve (+refinement last iter) + radix top-32 + residual ----------------
// grid BD, block 512
__global__ void k_solvethresh(const float* __restrict__ meas, int refine) {
    int b = blockIdx.x;
    if (g_done[b]) return;
    int s = g_scount[b];
    int spad = (s + 15) & ~15;
    int t = threadIdx.x;
    int lane = t & 31, wd = t >> 5;
    __shared__ float cs[SMX], sl[SMX], rs[SMX];
    cs[t] = (t < s) ? g_c[b][t] : 0.f;
    __syncthreads();
    float v0;
    MATVEC16(g_H, cs, v0)
    float solv;
    if (refine) {
        sl[t] = (t < s) ? v0 : 0.f;
        __syncthreads();
        float v1;
        MATVEC16(g_G, sl, v1)
        rs[t] = (t < s) ? (cs[t] - v1) : 0.f;
        __syncthreads();
        float v2;
        MATVEC16(g_H, rs, v2)
        solv = (t < s) ? (sl[t] + v2) : 0.f;
    } else {
        solv = (t < s) ? v0 : 0.f;
    }
    // --- radix select top-32 of |solv| ---
    __shared__ int hist[256];
    __shared__ unsigned sh_pref; __shared__ int sh_need;
    unsigned key = (t < s) ? __float_as_uint(fabsf(solv)) : 0u;
    unsigned pref = 0; int need = KK;
    for (int shift = 24; shift >= 0; shift -= 8) {
        unsigned mhi = (shift == 24) ? 0u : (0xFFFFFFFFu << (shift + 8));
        if (t < 256) hist[t] = 0;
        __syncthreads();
        if ((key & mhi) == pref) atomicAdd(&hist[(key >> shift) & 255], 1);
        __syncthreads();
        if (t < 32) {
            int base = 255 - 8 * t;
            int cnt[8]; int ssum = 0;
            #pragma unroll
            for (int q = 0; q < 8; q++) { cnt[q] = hist[base - q]; ssum += cnt[q]; }
            int incl = ssum;
            #pragma unroll
            for (int off = 1; off < 32; off <<= 1) {
                int v = __shfl_up_sync(0xffffffffu, incl, off);
                if (t >= off) incl += v;
            }
            int excl = incl - ssum;
            if (excl < need && need <= incl) {
                int cum = excl;
                #pragma unroll
                for (int q = 0; q < 8; q++) {
                    cum += cnt[q];
                    if (cum >= need) {
                        sh_pref = pref | ((unsigned)(base - q) << shift);
                        sh_need = need - (cum - cnt[q]);
                        break;
                    }
                }
            }
        }
        __syncthreads();
        pref = sh_pref; need = sh_need;
        __syncthreads();
    }
    unsigned T = pref;
    // --- tie resolution by smallest column id ---
    __shared__ int eqsl[SMX]; __shared__ int neq;
    __shared__ unsigned char self_[SMX];
    bool isgt = (key > T) && (t < s);
    bool iseq = (key == T) && (t < s);
    self_[t] = isgt ? 1 : 0;
    if (t == 0) neq = 0;
    __syncthreads();
    if (iseq) { int p = atomicAdd(&neq, 1); eqsl[p] = t; }
    __syncthreads();
    if (t == 0) {
        for (int r = 0; r < need; r++) {
            int bestc = 0x7fffffff, bi = -1;
            for (int q = 0; q < neq; q++) {
                int slot = eqsl[q];
                if (!self_[slot]) { int c = g_suplist[b][slot]; if (c < bestc) { bestc = c; bi = slot; } }
            }
            if (bi >= 0) self_[bi] = 1;
        }
    }
    __syncthreads();
    // --- gather selected 32 in slot order ---
    __shared__ int wsum[16]; __shared__ float pv[KK]; __shared__ int pp[KK];
    __shared__ float rn[16];
    bool sel = self_[t] != 0;
    unsigned bsel = __ballot_sync(0xffffffffu, sel);
    if (lane == 0) wsum[wd] = __popc(bsel);
    __syncthreads();
    int pre = 0;
    #pragma unroll
    for (int w = 0; w < 16; w++) if (w < wd) pre += wsum[w];
    int rank = pre + __popc(bsel & ((1u << lane) - 1));
    if (sel) { pp[rank] = t; pv[rank] = solv; }
    __syncthreads();
    if (t < KK) { g_xcols[b][t] = g_suplist[b][pp[t]]; g_xvals[b][t] = pv[t]; }
    // --- residual update + norm ---
    float nrm = 0.f;
    for (int m = t; m < MD; m += 512) {
        float r = meas[(size_t)b * MD + m];
        #pragma unroll
        for (int j = 0; j < KK; j++) r = fmaf(-pv[j], g_P[b][pp[j]][m], r);
        g_rT[m][b] = r;
        nrm = fmaf(r, r, nrm);
    }
    #pragma unroll
    for (int off = 16; off; off >>= 1) nrm += __shfl_down_sync(0xffffffffu, nrm, off);
    if (lane == 0) rn[wd] = nrm;
    __syncthreads();
    if (t == 0) {
        float tot = 0.f;
        #pragma unroll
        for (int w = 0; w < 16; w++) tot += rn[w];
        if (tot < TOLSQ) g_done[b] = 1;
    }
}

// ---------------- output ----------------
__global__ void k_out(float* __restrict__ out) {
    int b = blockIdx.x, t = threadIdx.x;
    for (int n = t; n < ND; n += 512) out[(size_t)b * ND + n] = 0.f;
    __syncthreads();
    if (t < KK) out[(size_t)b * ND + g_xcols[b][t]] = g_xvals[b][t];
}

extern "C" void kernel_launch(void* const* d_in, const int* in_sizes, int n_in,
                              void* d_out, int out_size) {
    const float* meas = (const float*)d_in[0];
    const float* A    = (const float*)d_in[1];
    if (n_in >= 2 && in_sizes[0] != BD * MD) {
        meas = (const float*)d_in[1];
        A    = (const float*)d_in[0];
    }
    float* out = (float*)d_out;

    int smem4 = 4 * TILE * 4;   // 69632 B
    int smem3 = 3 * TILE * 4;   // 52224 B
    cudaFuncSetAttribute(k_gram,  cudaFuncAttributeMaxDynamicSharedMemorySize, smem4);
    cudaFuncSetAttribute(k_T1,    cudaFuncAttributeMaxDynamicSharedMemorySize, smem4);
    cudaFuncSetAttribute(k_T2H11, cudaFuncAttributeMaxDynamicSharedMemorySize, smem3);

    k_transpose<<<dim3(ND / 32, MD / 32), dim3(32, 8)>>>(A);
    k_init<<<2048, 256>>>(meas);
    for (int it = 0; it < NITER; it++) {
        k_proxy<<<dim3(4, 4, MSPLIT), 256>>>(A);
        k_topk<<<BD, 512>>>(meas);
        k_gram<<<dim3(BD, 8), 256, smem4>>>();
        k_T1<<<dim3(BD, 8), 256, smem4>>>();
        k_SSinv<<<BD, 512>>>();
        k_T2H11<<<dim3(BD, 8), 256, smem3>>>();
        k_solvethresh<<<BD, 512>>>(meas, it == NITER - 1 ? 1 : 0);
    }
    k_out<<<BD, 512>>>(out);
}

// round 8
// speedup vs baseline: 2.2132x; 1.0008x over previous
#include <cuda_runtime.h>
#include <math.h>

#define MD 1024
#define ND 4096
#define BD 16
#define KK 32
#define KK2 64
#define SMX 512
#define NITER 8
#define MSPLIT 8
#define TOLSQ (1e-6f * 1e-6f)
#define PAD 68
#define TILE (64 * PAD)   // floats per smem tile

typedef unsigned long long u64_t;
__device__ __forceinline__ void fma2(u64_t &d, u64_t a, u64_t b) {
    asm("fma.rn.f32x2 %0, %1, %2, %0;" : "+l"(d) : "l"(a), "l"(b));
}
__device__ __forceinline__ float acc2sum(u64_t v) {
    float lo, hi; asm("mov.b64 {%0,%1}, %2;" : "=f"(lo), "=f"(hi) : "l"(v)); return lo + hi;
}
__device__ __forceinline__ void cpa16(float* dst, const float* src) {
    unsigned d = (unsigned)__cvta_generic_to_shared(dst);
    asm volatile("cp.async.cg.shared.global [%0], [%1], 16;" :: "r"(d), "l"(src) : "memory");
}
__device__ __forceinline__ void cpcommit() { asm volatile("cp.async.commit_group;" ::: "memory"); }
__device__ __forceinline__ void cpwait0()  { asm volatile("cp.async.wait_group 0;" ::: "memory"); }
__device__ __forceinline__ void cpwait1()  { asm volatile("cp.async.wait_group 1;" ::: "memory"); }

// ---------------- persistent device state ----------------
__device__ __align__(16) float g_AT[ND][MD];
__device__ __align__(16) float g_rT[MD][BD];
__device__ __align__(16) float g_partial[MSPLIT][BD][ND];
__device__ unsigned char g_support[BD][ND];
__device__ int   g_suplist[BD][SMX];
__device__ int   g_scount[BD];
__device__ int   g_sold[BD];
__device__ int   g_done[BD];
__device__ __align__(16) float g_P[BD][SMX][MD];
__device__ __align__(16) float g_G[BD][SMX][SMX];   // zero beyond s (invariant)
__device__ __align__(16) float g_H[BD][SMX][SMX];   // zero beyond s (invariant)
__device__ float g_c[BD][SMX];
__device__ __align__(16) float g_T1[BD][SMX][KK2];  // zero rows >= so (invariant)
__device__ float g_Sinv[BD][KK2][KK2];
__device__ int   g_xcols[BD][KK];
__device__ float g_xvals[BD][KK];

// ---------------- one-time: transpose A ----------------
__global__ void k_transpose(const float* __restrict__ A) {
    __shared__ float tile[32][33];
    int nb = blockIdx.x * 32, mb = blockIdx.y * 32;
    int tx = threadIdx.x, ty = threadIdx.y;
    for (int i = ty; i < 32; i += 8)
        tile[i][tx] = A[(size_t)(mb + i) * ND + nb + tx];
    __syncthreads();
    for (int i = ty; i < 32; i += 8)
        g_AT[nb + i][mb + tx] = tile[tx][i];
}

// ---------------- init: state + zero-invariant for G/H/T1 ----------------
// grid 2048, block 256
__global__ void k_init(const float* __restrict__ meas) {
    long i = (long)blockIdx.x * blockDim.x + threadIdx.x;
    long stride = (long)gridDim.x * blockDim.x;
    float4 z4 = make_float4(0.f, 0.f, 0.f, 0.f);
    long ng = (long)BD * SMX * SMX / 4;
    float4* pg = (float4*)g_G;
    for (long k = i; k < ng; k += stride) pg[k] = z4;
    float4* ph = (float4*)g_H;
    for (long k = i; k < ng; k += stride) ph[k] = z4;
    long nt = (long)BD * SMX * KK2 / 4;
    float4* pt = (float4*)g_T1;
    for (long k = i; k < nt; k += stride) pt[k] = z4;
    for (long k = i; k < (long)BD * ND; k += stride) g_support[k / ND][k % ND] = 0;
    if (i < BD * MD) { int b = (int)(i / MD), m = (int)(i % MD); g_rT[m][b] = meas[b * MD + m]; }
    if (i < BD) { g_scount[i] = 0; g_sold[i] = 0; g_done[i] = 0; }
}

// ---------------- proxy = A^T r, m-split partials ----------------
// grid (4, 4, MSPLIT), block 256
__global__ void k_proxy(const float* __restrict__ A) {
    int t  = threadIdx.x;
    int n0 = (blockIdx.x * 256 + t) * 4;
    int bg = blockIdx.y * 4;
    int mz = blockIdx.z;
    int m0 = mz * (MD / MSPLIT);
    float acc[4][4] = {};
    #pragma unroll 4
    for (int mm = 0; mm < MD / MSPLIT; mm++) {
        int m = m0 + mm;
        float4 a  = *(const float4*)(A + (size_t)m * ND + n0);
        float4 rv = *(const float4*)(&g_rT[m][bg]);
        acc[0][0] = fmaf(a.x, rv.x, acc[0][0]); acc[0][1] = fmaf(a.y, rv.x, acc[0][1]);
        acc[0][2] = fmaf(a.z, rv.x, acc[0][2]); acc[0][3] = fmaf(a.w, rv.x, acc[0][3]);
        acc[1][0] = fmaf(a.x, rv.y, acc[1][0]); acc[1][1] = fmaf(a.y, rv.y, acc[1][1]);
        acc[1][2] = fmaf(a.z, rv.y, acc[1][2]); acc[1][3] = fmaf(a.w, rv.y, acc[1][3]);
        acc[2][0] = fmaf(a.x, rv.z, acc[2][0]); acc[2][1] = fmaf(a.y, rv.z, acc[2][1]);
        acc[2][2] = fmaf(a.z, rv.z, acc[2][2]); acc[2][3] = fmaf(a.w, rv.z, acc[2][3]);
        acc[3][0] = fmaf(a.x, rv.w, acc[3][0]); acc[3][1] = fmaf(a.y, rv.w, acc[3][1]);
        acc[3][2] = fmaf(a.z, rv.w, acc[3][2]); acc[3][3] = fmaf(a.w, rv.w, acc[3][3]);
    }
    #pragma unroll
    for (int bb = 0; bb < 4; bb++) {
        float4 v = make_float4(acc[bb][0], acc[bb][1], acc[bb][2], acc[bb][3]);
        *(float4*)(&g_partial[mz][bg + bb][n0]) = v;
    }
}

// ---------------- radix-select top-64 + support update + fused pack ----------------
// grid BD, block 512
__global__ void k_topk(const float* __restrict__ meas) {
    const int BT = 512;
    int b = blockIdx.x;
    if (g_done[b]) return;
    __shared__ unsigned keys[ND];
    __shared__ float ysh[MD];
    __shared__ int hist[4][256];
    __shared__ unsigned sh_pref; __shared__ int sh_need;
    __shared__ int eqlist[128];
    __shared__ int sh_neq, sh_app, sh_sold;
    int t = threadIdx.x;
    int lane = t & 31, wd = t >> 5;
    for (int n = t; n < ND; n += BT) {
        float s = 0.f;
        #pragma unroll
        for (int ms = 0; ms < MSPLIT; ms++) s += g_partial[ms][b][n];
        keys[n] = __float_as_uint(fabsf(s));
    }
    for (int m = t; m < MD; m += BT) ysh[m] = meas[(size_t)b * MD + m];
    if (t == 0) { sh_sold = g_scount[b]; sh_app = sh_sold; sh_neq = 0; }
    __syncthreads();
    unsigned pref = 0; int need = 2 * KK;
    for (int shift = 24; shift >= 0; shift -= 8) {
        unsigned mhi = (shift == 24) ? 0u : (0xFFFFFFFFu << (shift + 8));
        for (int i = t; i < 1024; i += BT) hist[i >> 8][i & 255] = 0;
        __syncthreads();
        int hs = wd & 3;
        for (int n = t; n < ND; n += BT) {
            unsigned k = keys[n];
            if ((k & mhi) == pref) atomicAdd(&hist[hs][(k >> shift) & 255], 1);
        }
        __syncthreads();
        if (t < 256) hist[0][t] += hist[1][t] + hist[2][t] + hist[3][t];
        __syncthreads();
        if (t < 32) {
            int base = 255 - 8 * t;
            int cnt[8]; int ssum = 0;
            #pragma unroll
            for (int q = 0; q < 8; q++) { cnt[q] = hist[0][base - q]; ssum += cnt[q]; }
            int incl = ssum;
            #pragma unroll
            for (int off = 1; off < 32; off <<= 1) {
                int v = __shfl_up_sync(0xffffffffu, incl, off);
                if (t >= off) incl += v;
            }
            int excl = incl - ssum;
            if (excl < need && need <= incl) {
                int cum = excl;
                #pragma unroll
                for (int q = 0; q < 8; q++) {
                    cum += cnt[q];
                    if (cum >= need) {
                        sh_pref = pref | ((unsigned)(base - q) << shift);
                        sh_need = need - (cum - cnt[q]);
                        break;
                    }
                }
            }
        }
        __syncthreads();
        pref = sh_pref; need = sh_need;
        __syncthreads();
    }
    unsigned T = pref;
    for (int n = t; n < ND; n += BT) {
        unsigned k = keys[n];
        if (k > T) {
            if (!g_support[b][n]) {
                g_support[b][n] = 1;
                int p = atomicAdd(&sh_app, 1);
                g_suplist[b][p] = n;
            }
        } else if (k == T) {
            int q = atomicAdd(&sh_neq, 1);
            if (q < 128) eqlist[q] = n;
        }
    }
    __syncthreads();
    if (t == 0) {
        int ne = sh_neq < 128 ? sh_neq : 128;
        for (int r = 0; r < need; r++) {           // jax ties: smallest index first
            int best = 0x7fffffff, bi = -1;
            for (int q = 0; q < ne; q++) {
                int n = eqlist[q];
                if (n >= 0 && n < best) { best = n; bi = q; }
            }
            if (bi < 0) break;
            eqlist[bi] = -1;
            if (!g_support[b][best]) {
                g_support[b][best] = 1;
                g_suplist[b][sh_app++] = best;
            }
        }
        g_sold[b] = sh_sold;
        g_scount[b] = sh_app;
    }
    __syncthreads();
    // ---- fused pack: high-MLP copy + dot (warp per column) ----
    int so = sh_sold, s = sh_app, nn = s - so;
    for (int p = wd; p < nn; p += 16) {
        int col = g_suplist[b][so + p];
        const float4* Ac = (const float4*)g_AT[col];
        float4* Pd = (float4*)g_P[b][so + p];
        float4 v[8];
        #pragma unroll
        for (int i = 0; i < 8; i++) v[i] = Ac[i * 32 + lane];
        float acc = 0.f;
        #pragma unroll
        for (int i = 0; i < 8; i++) {
            Pd[i * 32 + lane] = v[i];
            const float4 yv = *(const float4*)&ysh[(i * 32 + lane) * 4];
            acc = fmaf(v[i].x, yv.x, fmaf(v[i].y, yv.y, fmaf(v[i].z, yv.z, fmaf(v[i].w, yv.w, acc))));
        }
        #pragma unroll
        for (int off = 16; off; off >>= 1) acc += __shfl_down_sync(0xffffffffu, acc, off);
        if (lane == 0) g_c[b][so + p] = acc;
    }
}

// ======== 64x64 microkernel: strided mapping, conflict-free LDS.128 ========
#define MICROKERNEL(ASRC, BSRC)                                               \
    {                                                                         \
        _Pragma("unroll")                                                     \
        for (int k4 = 0; k4 < 16; k4++) {                                     \
            ulonglong2 rv[4], cv[4];                                          \
            _Pragma("unroll")                                                 \
            for (int i = 0; i < 4; i++)                                       \
                rv[i] = *(const ulonglong2*)&(ASRC)[(ty + 16 * i) * PAD + k4 * 4]; \
            _Pragma("unroll")                                                 \
            for (int j = 0; j < 4; j++)                                       \
                cv[j] = *(const ulonglong2*)&(BSRC)[(tx + 16 * j) * PAD + k4 * 4]; \
            _Pragma("unroll")                                                 \
            for (int i = 0; i < 4; i++)                                       \
                _Pragma("unroll")                                             \
                for (int j = 0; j < 4; j++) {                                 \
                    fma2(acc2[i][j], rv[i].x, cv[j].x);                       \
                    fma2(acc2[i][j], rv[i].y, cv[j].y);                       \
                }                                                             \
        }                                                                     \
    }

// cp.async tile load: 64 rows x 16 float4, 256 threads, 4 per thread per array
#define LOAD2(Ad, Bd, ASRCROW, BSRCROW, K0)                                   \
    {                                                                         \
        _Pragma("unroll")                                                     \
        for (int q = 0; q < 4; q++) {                                         \
            int idx = t + 256 * q;                                            \
            int r = idx >> 4, f = (idx & 15) * 4;                             \
            cpa16(&(Ad)[r * PAD + f], &(ASRCROW)[(K0) + f]);                  \
            cpa16(&(Bd)[r * PAD + f], &(BSRCROW)[(K0) + f]);                  \
        }                                                                     \
        cpcommit();                                                           \
    }

// ---------------- Gram new rows: G[so+r][c] = Pnew @ Pall^T (pipelined) ----------------
// grid (BD, 8), block 256, dyn smem 4*TILE floats
__global__ void k_gram(void) {
    int b = blockIdx.x;
    if (g_done[b]) return;
    int so = g_sold[b], s = g_scount[b], nn = s - so;
    if (nn == 0) return;
    int c0 = blockIdx.y * 64;
    if (c0 >= s) return;
    extern __shared__ float sm[];
    float* Ab = sm;            // 2 tiles
    float* Bb = sm + 2 * TILE; // 2 tiles
    int t = threadIdx.x;
    int ty = t >> 4, tx = t & 15;
    u64_t acc2[4][4] = {};
    {
        #pragma unroll
        for (int q = 0; q < 4; q++) {
            int idx = t + 256 * q; int r = idx >> 4, f = (idx & 15) * 4;
            int ra = so + r; ra = ra < SMX ? ra : SMX - 1;   // clamp (garbage rows never stored)
            cpa16(&Ab[r * PAD + f], &g_P[b][ra][f]);
            cpa16(&Bb[r * PAD + f], &g_P[b][c0 + r][f]);
        }
        cpcommit();
    }
    for (int step = 0; step < 16; step++) {
        int cur = step & 1;
        if (step < 15) {
            float* Ad = Ab + (cur ^ 1) * TILE;
            float* Bd = Bb + (cur ^ 1) * TILE;
            int k0 = (step + 1) * 64;
            #pragma unroll
            for (int q = 0; q < 4; q++) {
                int idx = t + 256 * q; int r = idx >> 4, f = (idx & 15) * 4;
                int ra = so + r; ra = ra < SMX ? ra : SMX - 1;
                cpa16(&Ad[r * PAD + f], &g_P[b][ra][k0 + f]);
                cpa16(&Bd[r * PAD + f], &g_P[b][c0 + r][k0 + f]);
            }
            cpcommit();
            cpwait1();
        } else cpwait0();
        __syncthreads();
        const float* As = Ab + cur * TILE;
        const float* Bs = Bb + cur * TILE;
        MICROKERNEL(As, Bs)
        __syncthreads();
    }
    #pragma unroll
    for (int i = 0; i < 4; i++) {
        int r = ty + 16 * i; if (r >= nn) continue;
        #pragma unroll
        for (int j = 0; j < 4; j++) {
            int c = c0 + tx + 16 * j; if (c >= s) continue;
            float v = acc2sum(acc2[i][j]);
            g_G[b][so + r][c] = v;
            g_G[b][c][so + r] = v;
        }
    }
}

// ---------------- T1: acc[c][r] = sum_k G[so+c][k] H[r][k] (pipelined, guard-free) ----------------
// grid (BD, 8), block 256, dyn smem 4*TILE floats
__global__ void k_T1(void) {
    int b = blockIdx.x;
    if (g_done[b]) return;
    int so = g_sold[b], s = g_scount[b], nn = s - so;
    if (nn == 0) return;
    int r0 = blockIdx.y * 64;
    if (r0 >= so) return;
    extern __shared__ float sm[];
    float* Ab = sm;
    float* Bb = sm + 2 * TILE;
    int t = threadIdx.x;
    int ty = t >> 4, tx = t & 15;
    int NS = (so + 63) >> 6;
    u64_t acc2[4][4] = {};
    {
        #pragma unroll
        for (int q = 0; q < 4; q++) {
            int idx = t + 256 * q; int r = idx >> 4, f = (idx & 15) * 4;
            int ra = so + r; ra = ra < SMX ? ra : SMX - 1;
            cpa16(&Ab[r * PAD + f], &g_G[b][ra][f]);       // rows >= s are zero (invariant)
            cpa16(&Bb[r * PAD + f], &g_H[b][r0 + r][f]);   // rows/cols >= so are zero
        }
        cpcommit();
    }
    for (int step = 0; step < NS; step++) {
        int cur = step & 1;
        if (step + 1 < NS) {
            float* Ad = Ab + (cur ^ 1) * TILE;
            float* Bd = Bb + (cur ^ 1) * TILE;
            int k0 = (step + 1) * 64;
            #pragma unroll
            for (int q = 0; q < 4; q++) {
                int idx = t + 256 * q; int r = idx >> 4, f = (idx & 15) * 4;
                int ra = so + r; ra = ra < SMX ? ra : SMX - 1;
                cpa16(&Ad[r * PAD + f], &g_G[b][ra][k0 + f]);
                cpa16(&Bd[r * PAD + f], &g_H[b][r0 + r][k0 + f]);
            }
            cpcommit();
            cpwait1();
        } else cpwait0();
        __syncthreads();
        const float* As = Ab + cur * TILE;
        const float* Bs = Bb + cur * TILE;
        MICROKERNEL(As, Bs)
        __syncthreads();
    }
    #pragma unroll
    for (int i = 0; i < 4; i++) {
        int c = ty + 16 * i;
        #pragma unroll
        for (int j = 0; j < 4; j++) {
            int r = r0 + tx + 16 * j;
            g_T1[b][r][c] = acc2sum(acc2[i][j]);  // rows >= so store exact 0 (keeps invariant)
        }
    }
}

// ---------------- fused: S = G22 - G21 T1 -> GJ inverse -> Sinv, H22 ----------------
// grid BD, block 512 (guard-free k loops via zero invariant)
__global__ void k_SSinv(void) {
    int b = blockIdx.x;
    if (g_done[b]) return;
    int so = g_sold[b], s = g_scount[b], nn = s - so;
    if (nn == 0) return;
    __shared__ float Gs[64][65], Ts[64][65];
    __shared__ float pivrow[128], fcol[64], sh_piv;
    int t = threadIdx.x;
    int i = t >> 3, jg = t & 7;
    float accs[8] = {};
    for (int k0 = 0; k0 < so; k0 += 64) {
        for (int idx = t; idx < 64 * 64; idx += 512) {
            int rr = idx >> 6, kk = idx & 63;
            int ra = so + rr; ra = ra < SMX ? ra : SMX - 1;
            Gs[rr][kk] = g_G[b][ra][k0 + kk];          // k >= so pairs with zero T1 rows
            int j = idx & 63, k2 = idx >> 6;
            Ts[k2][j] = g_T1[b][k0 + k2][j];           // rows >= so are zero
        }
        __syncthreads();
        #pragma unroll 8
        for (int k = 0; k < 64; k++) {
            float gv = Gs[i][k];
            #pragma unroll
            for (int jj = 0; jj < 8; jj++) accs[jj] = fmaf(gv, Ts[k][jg * 8 + jj], accs[jj]);
        }
        __syncthreads();
    }
    #pragma unroll
    for (int jj = 0; jj < 8; jj++) {
        int j = jg * 8 + jj;
        float v;
        if (i < nn && j < nn) v = g_G[b][so + i][so + j] - accs[jj];
        else v = (i == j) ? 1.f : 0.f;
        Gs[i][j] = v;
    }
    __syncthreads();
    int row = t >> 3, cg = t & 7;
    float a[16];
    #pragma unroll
    for (int cc = 0; cc < 16; cc++) {
        int c = cg * 16 + cc;
        a[cc] = (c < 64) ? Gs[row][c] : ((c - 64 == row) ? 1.f : 0.f);
    }
    __syncthreads();
    for (int j = 0; j < 64; j++) {
        if (row == j && cg == (j >> 4)) sh_piv = a[j & 15];
        __syncthreads();
        float inv = 1.f / sh_piv;
        if (row == j) {
            #pragma unroll
            for (int cc = 0; cc < 16; cc++) { a[cc] *= inv; pivrow[cg * 16 + cc] = a[cc]; }
        }
        if (cg == (j >> 4)) fcol[row] = a[j & 15];
        __syncthreads();
        float f = (row == j) ? 0.f : fcol[row];
        #pragma unroll
        for (int cc = 0; cc < 16; cc++) a[cc] = fmaf(-f, pivrow[cg * 16 + cc], a[cc]);
    }
    __syncthreads();
    #pragma unroll
    for (int cc = 0; cc < 16; cc++) {
        int c = cg * 16 + cc;
        if (c >= 64) {
            int j = c - 64;
            g_Sinv[b][row][j] = a[cc];
            if (row < nn && j < nn) g_H[b][so + row][so + j] = a[cc];
        }
    }
}

// ---------------- fused T2 + H11 (phase B pipelined) ----------------
// grid (BD, 8), block 256, dyn smem 3*TILE floats
__global__ void k_T2H11(void) {
    int b = blockIdx.x;
    if (g_done[b]) return;
    int so = g_sold[b], s = g_scount[b], nn = s - so;
    if (nn == 0) return;
    int r0 = blockIdx.y * 64;
    if (r0 >= so) return;
    extern __shared__ float sm[];
    float* As = sm;            // 1 tile (T1 rows, then T2)
    float* Bb = sm + TILE;     // 2 tiles
    int t = threadIdx.x;
    int ty = t >> 4, tx = t & 15;
    // phase A: T2[r][c] = sum_k T1[r][k] * Sinv[c][k]
    {
        #pragma unroll
        for (int q = 0; q < 4; q++) {
            int idx = t + 256 * q; int r = idx >> 4, f = (idx & 15) * 4;
            cpa16(&As[r * PAD + f], &g_T1[b][r0 + r][f]);
            cpa16(&Bb[r * PAD + f], &g_Sinv[b][r][f]);
        }
        cpcommit(); cpwait0();
    }
    __syncthreads();
    u64_t acc2[4][4] = {};
    MICROKERNEL(As, Bb)
    float t2v[4][4];
    #pragma unroll
    for (int i = 0; i < 4; i++)
        #pragma unroll
        for (int j = 0; j < 4; j++) t2v[i][j] = acc2sum(acc2[i][j]);
    #pragma unroll
    for (int i = 0; i < 4; i++) {
        int r = r0 + ty + 16 * i; if (r >= so) continue;
        #pragma unroll
        for (int j = 0; j < 4; j++) {
            int cx = tx + 16 * j;
            if (cx < nn) { g_H[b][r][so + cx] = -t2v[i][j]; g_H[b][so + cx][r] = -t2v[i][j]; }
        }
    }
    __syncthreads();   // all phase-A reads done
    #pragma unroll
    for (int i = 0; i < 4; i++)
        #pragma unroll
        for (int j = 0; j < 4; j++) As[(ty + 16 * i) * PAD + tx + 16 * j] = t2v[i][j];
    // phase B: H11[r][c] += sum_k T2[r][k] * T1[c][k]  (pipelined over c0)
    int NS = (so + 63) >> 6;
    {
        #pragma unroll
        for (int q = 0; q < 4; q++) {
            int idx = t + 256 * q; int r = idx >> 4, f = (idx & 15) * 4;
            cpa16(&Bb[r * PAD + f], &g_T1[b][r][f]);
        }
        cpcommit();
    }
    for (int step = 0; step < NS; step++) {
        int cur = step & 1;
        if (step + 1 < NS) {
            float* Bd = Bb + (cur ^ 1) * TILE;
            int c0n = (step + 1) * 64;
            #pragma unroll
            for (int q = 0; q < 4; q++) {
                int idx = t + 256 * q; int r = idx >> 4, f = (idx & 15) * 4;
                cpa16(&Bd[r * PAD + f], &g_T1[b][c0n + r][f]);
            }
            cpcommit();
            cpwait1();
        } else cpwait0();
        __syncthreads();
        const float* Bs = Bb + cur * TILE;
        u64_t accb[4][4] = {};
        {
            u64_t (&acc2)[4][4] = accb;
            MICROKERNEL(As, Bs)
        }
        int c0 = step * 64;
        #pragma unroll
        for (int i = 0; i < 4; i++) {
            int r = r0 + ty + 16 * i; if (r >= so) continue;
            #pragma unroll
            for (int j = 0; j < 4; j++) {
                int c = c0 + tx + 16 * j; if (c >= so) continue;
                g_H[b][r][c] += acc2sum(accb[i][j]);
            }
        }
        __syncthreads();
    }
}

// high-MLP matvec over zero-padded rows
#define MATVEC16(W, VEC, OUTVAR)                                   \
    {                                                              \
        float a0 = 0.f, a1 = 0.f, a2 = 0.f, a3 = 0.f;              \
        for (int j0 = 0; j0 < spad; j0 += 16) {                    \
            _Pragma("unroll")                                      \
            for (int jj = 0; jj < 16; jj += 4) {                   \
                a0 = fmaf(W[b][j0 + jj + 0][t], VEC[j0 + jj + 0], a0); \
                a1 = fmaf(W[b][j0 + jj + 1][t], VEC[j0 + jj + 1], a1); \
                a2 = fmaf(W[b][j0 + jj + 2][t], VEC[j0 + jj + 2], a2); \
                a3 = fmaf(W[b][j0 + jj + 3][t], VEC[j0 + jj + 3], a3); \
            }                                                      \
        }                                                          \
        OUTVAR = ((a0 + a1) + (a2 + a3));                          \
    }

// ---------------- fused solve (+refinement last iter) + radix top-32 + residual ----------------
// grid BD, block 512
__global__ void k_solvethresh(const float* __restrict__ meas, int refine) {
    int b = blockIdx.x;
    if (g_done[b]) return;
    int s = g_scount[b];
    int spad = (s + 15) & ~15;
    int t = threadIdx.x;
    int lane = t & 31, wd = t >> 5;
    __shared__ float cs[SMX], sl[SMX], rs[SMX];
    cs[t] = (t < s) ? g_c[b][t] : 0.f;
    __syncthreads();
    float v0;
    MATVEC16(g_H, cs, v0)
    float solv;
    if (refine) {
        sl[t] = (t < s) ? v0 : 0.f;
        __syncthreads();
        float v1;
        MATVEC16(g_G, sl, v1)
        rs[t] = (t < s) ? (cs[t] - v1) : 0.f;
        __syncthreads();
        float v2;
        MATVEC16(g_H, rs, v2)
        solv = (t < s) ? (sl[t] + v2) : 0.f;
    } else {
        solv = (t < s) ? v0 : 0.f;
    }
    // --- radix select top-32 of |solv| ---
    __shared__ int hist[256];
    __shared__ unsigned sh_pref; __shared__ int sh_need;
    unsigned key = (t < s) ? __float_as_uint(fabsf(solv)) : 0u;
    unsigned pref = 0; int need = KK;
    for (int shift = 24; shift >= 0; shift -= 8) {
        unsigned mhi = (shift == 24) ? 0u : (0xFFFFFFFFu << (shift + 8));
        if (t < 256) hist[t] = 0;
        __syncthreads();
        if ((key & mhi) == pref) atomicAdd(&hist[(key >> shift) & 255], 1);
        __syncthreads();
        if (t < 32) {
            int base = 255 - 8 * t;
            int cnt[8]; int ssum = 0;
            #pragma unroll
            for (int q = 0; q < 8; q++) { cnt[q] = hist[base - q]; ssum += cnt[q]; }
            int incl = ssum;
            #pragma unroll
            for (int off = 1; off < 32; off <<= 1) {
                int v = __shfl_up_sync(0xffffffffu, incl, off);
                if (t >= off) incl += v;
            }
            int excl = incl - ssum;
            if (excl < need && need <= incl) {
                int cum = excl;
                #pragma unroll
                for (int q = 0; q < 8; q++) {
                    cum += cnt[q];
                    if (cum >= need) {
                        sh_pref = pref | ((unsigned)(base - q) << shift);
                        sh_need = need - (cum - cnt[q]);
                        break;
                    }
                }
            }
        }
        __syncthreads();
        pref = sh_pref; need = sh_need;
        __syncthreads();
    }
    unsigned T = pref;
    // --- tie resolution by smallest column id ---
    __shared__ int eqsl[SMX]; __shared__ int neq;
    __shared__ unsigned char self_[SMX];
    bool isgt = (key > T) && (t < s);
    bool iseq = (key == T) && (t < s);
    self_[t] = isgt ? 1 : 0;
    if (t == 0) neq = 0;
    __syncthreads();
    if (iseq) { int p = atomicAdd(&neq, 1); eqsl[p] = t; }
    __syncthreads();
    if (t == 0) {
        for (int r = 0; r < need; r++) {
            int bestc = 0x7fffffff, bi = -1;
            for (int q = 0; q < neq; q++) {
                int slot = eqsl[q];
                if (!self_[slot]) { int c = g_suplist[b][slot]; if (c < bestc) { bestc = c; bi = slot; } }
            }
            if (bi >= 0) self_[bi] = 1;
        }
    }
    __syncthreads();
    // --- gather selected 32 in slot order ---
    __shared__ int wsum[16]; __shared__ float pv[KK]; __shared__ int pp[KK];
    __shared__ float rn[16];
    bool sel = self_[t] != 0;
    unsigned bsel = __ballot_sync(0xffffffffu, sel);
    if (lane == 0) wsum[wd] = __popc(bsel);
    __syncthreads();
    int pre = 0;
    #pragma unroll
    for (int w = 0; w < 16; w++) if (w < wd) pre += wsum[w];
    int rank = pre + __popc(bsel & ((1u << lane) - 1));
    if (sel) { pp[rank] = t; pv[rank] = solv; }
    __syncthreads();
    if (t < KK) { g_xcols[b][t] = g_suplist[b][pp[t]]; g_xvals[b][t] = pv[t]; }
    // --- residual update + norm ---
    float nrm = 0.f;
    for (int m = t; m < MD; m += 512) {
        float r = meas[(size_t)b * MD + m];
        #pragma unroll
        for (int j = 0; j < KK; j++) r = fmaf(-pv[j], g_P[b][pp[j]][m], r);
        g_rT[m][b] = r;
        nrm = fmaf(r, r, nrm);
    }
    #pragma unroll
    for (int off = 16; off; off >>= 1) nrm += __shfl_down_sync(0xffffffffu, nrm, off);
    if (lane == 0) rn[wd] = nrm;
    __syncthreads();
    if (t == 0) {
        float tot = 0.f;
        #pragma unroll
        for (int w = 0; w < 16; w++) tot += rn[w];
        if (tot < TOLSQ) g_done[b] = 1;
    }
}

// ---------------- output ----------------
__global__ void k_out(float* __restrict__ out) {
    int b = blockIdx.x, t = threadIdx.x;
    for (int n = t; n < ND; n += 512) out[(size_t)b * ND + n] = 0.f;
    __syncthreads();
    if (t < KK) out[(size_t)b * ND + g_xcols[b][t]] = g_xvals[b][t];
}

extern "C" void kernel_launch(void* const* d_in, const int* in_sizes, int n_in,
                              void* d_out, int out_size) {
    const float* meas = (const float*)d_in[0];
    const float* A    = (const float*)d_in[1];
    if (n_in >= 2 && in_sizes[0] != BD * MD) {
        meas = (const float*)d_in[1];
        A    = (const float*)d_in[0];
    }
    float* out = (float*)d_out;

    int smem4 = 4 * TILE * 4;   // 69632 B
    int smem3 = 3 * TILE * 4;   // 52224 B
    cudaFuncSetAttribute(k_gram,  cudaFuncAttributeMaxDynamicSharedMemorySize, smem4);
    cudaFuncSetAttribute(k_T1,    cudaFuncAttributeMaxDynamicSharedMemorySize, smem4);
    cudaFuncSetAttribute(k_T2H11, cudaFuncAttributeMaxDynamicSharedMemorySize, smem3);

    k_transpose<<<dim3(ND / 32, MD / 32), dim3(32, 8)>>>(A);
    k_init<<<2048, 256>>>(meas);
    for (int it = 0; it < NITER; it++) {
        k_proxy<<<dim3(4, 4, MSPLIT), 256>>>(A);
        k_topk<<<BD, 512>>>(meas);
        k_gram<<<dim3(BD, 8), 256, smem4>>>();
        k_T1<<<dim3(BD, 8), 256, smem4>>>();
        k_SSinv<<<BD, 512>>>();
        k_T2H11<<<dim3(BD, 8), 256, smem3>>>();
        k_solvethresh<<<BD, 512>>>(meas, it == NITER - 1 ? 1 : 0);
    }
    k_out<<<BD, 512>>>(out);
}